// round 2
// baseline (speedup 1.0000x reference)
#include <cuda_runtime.h>
#include <math.h>
#include <stdint.h>

#define HDIM   1536
#define BB     4
#define SL     2048
#define NHEADS 12
#define HDH    128
#define MEMD   128
#define INNERD 6144
#define NT     (BB*SL)          // 8192 tokens
#define KW     4
#define CHUNK  64
#define NCHUNK (SL/CHUNK)       // 32
#define MT     8                // mem columns per scan block
#define QS     129              // padded smem row stride (bank-conflict-free)

// ------------------------------------------------------------------ scratch
__device__ float g_y   [(size_t)NT*HDIM];
__device__ float g_t0  [(size_t)NT*HDIM];
__device__ float g_t1  [(size_t)NT*HDIM];
__device__ float g_xh  [(size_t)NT*HDIM];
__device__ float g_h2  [(size_t)NT*HDIM];
__device__ float g_big [(size_t)NT*2*INNERD];
__device__ float g_ffn [(size_t)NT*INNERD];
__device__ float g_q   [(size_t)NT*4*HDH];
__device__ float g_k   [(size_t)NT*4*HDH];
__device__ float g_v   [(size_t)NT*4*HDH];
__device__ float g_rd  [(size_t)NT*4*HDH];
__device__ float g_mo  [(size_t)NT*4*HDH];
__device__ float g_gm  [(size_t)NT*4];
__device__ float g_hw  [(size_t)NT*NHEADS];
__device__ float g_gate[NT];

__constant__ int c_dils[NHEADS][3] = {
    {1,2,4},{1,1,1},{4,8,16},{8,16,32},{32,64,128},{64,128,256},
    {256,512,1024},{1,100,200},{1,500,1000},{1,1024,2048},{3,9,27},{5,25,125}};

__device__ __forceinline__ float sigf(float v){ return 1.f/(1.f+expf(-v)); }
__device__ __forceinline__ float geluf(float v){ return 0.5f*v*(1.f+erff(v*0.70710678118654752f)); }

// ------------------------------------------------------------ rms + gate (+router)
__global__ void __launch_bounds__(256) rms_router_kernel(
    const float* __restrict__ x, const float* __restrict__ nw,
    const float* __restrict__ gw, const float* __restrict__ gb,
    float* __restrict__ y, float* __restrict__ gate,
    const float* __restrict__ rw, const float* __restrict__ rb,
    float* __restrict__ hw)
{
    __shared__ float sy[HDIM];
    __shared__ float red[256];
    int t = blockIdx.x, tid = threadIdx.x;
    const float* xr = x + (size_t)t*HDIM;
    float ss = 0.f, gd = 0.f;
    for (int i = tid; i < HDIM; i += 256){
        float v = xr[i]; sy[i] = v; ss += v*v; gd += v*gw[i];
    }
    red[tid] = ss; __syncthreads();
    for (int s = 128; s > 0; s >>= 1){ if (tid < s) red[tid] += red[tid+s]; __syncthreads(); }
    float rs = rsqrtf(red[0]*(1.f/HDIM) + 1e-6f);
    __syncthreads();
    red[tid] = gd; __syncthreads();
    for (int s = 128; s > 0; s >>= 1){ if (tid < s) red[tid] += red[tid+s]; __syncthreads(); }
    if (tid == 0) gate[t] = sigf(red[0] + gb[0]);
    float* yr = y + (size_t)t*HDIM;
    for (int i = tid; i < HDIM; i += 256){
        float v = sy[i]*rs*nw[i]; yr[i] = v; sy[i] = v;
    }
    if (rw){
        __syncthreads();
        int warp = tid >> 5, lane = tid & 31;
        for (int r = warp; r < NHEADS; r += 8){
            float s = 0.f;
            for (int i = lane; i < HDIM; i += 32) s += sy[i]*rw[r*HDIM + i];
            #pragma unroll
            for (int o = 16; o; o >>= 1) s += __shfl_down_sync(0xffffffffu, s, o);
            if (lane == 0) hw[(size_t)t*NHEADS + r] = sigf(s + rb[r]);
        }
    }
}

// ------------------------------------------------------------ conv stack stage
__global__ void __launch_bounds__(256) convstack_kernel(
    const float* __restrict__ in, float* __restrict__ out,
    const float* __restrict__ w, const float* __restrict__ b, int dil)
{
    long idx = (long)blockIdx.x*256 + threadIdx.x;
    if (idx >= (long)NT*HDIM) return;
    int c = (int)(idx % HDIM);
    long row = idx / HDIM;
    int t = (int)(row % SL);
    float acc = b[c];
    #pragma unroll
    for (int k = 0; k < KW; k++){
        int tt = t - (KW-1-k)*dil;
        if (tt >= 0) acc += in[idx + (long)(tt - t)*HDIM] * w[c*KW + k];
    }
    out[idx] = in[idx] + geluf(acc);
}

// ------------------------------------------------------------ per-head conv stage
__global__ void __launch_bounds__(256) headconv_kernel(
    const float* __restrict__ in, float* __restrict__ out,
    const float* __restrict__ w, const float* __restrict__ b, int stage)
{
    long idx = (long)blockIdx.x*256 + threadIdx.x;
    if (idx >= (long)NT*HDIM) return;
    int d = (int)(idx & (HDH-1));
    int i = (int)((idx / HDH) % NHEADS);
    long tok = idx / HDIM;
    int t = (int)(tok % SL);
    int dil = c_dils[i][stage];
    const float* wp = w + ((i*3 + stage)*HDH + d)*KW;
    float acc = b[(i*3 + stage)*HDH + d];
    #pragma unroll
    for (int k = 0; k < KW; k++){
        int tt = t - (KW-1-k)*dil;
        if (tt >= 0) acc += in[idx + (long)(tt - t)*HDIM] * wp[k];
    }
    out[idx] = in[idx] + acc;
}

// ------------------------------------------------------------ combine heads
__global__ void __launch_bounds__(256) combine_kernel(
    const float* __restrict__ hbuf, const float* __restrict__ memout,
    const float* __restrict__ hw, float* __restrict__ out)
{
    long idx = (long)blockIdx.x*256 + threadIdx.x;
    if (idx >= (long)NT*HDIM) return;
    int d = (int)(idx & (HDH-1));
    int i = (int)((idx / HDH) % NHEADS);
    long tok = idx / HDIM;
    float v = hbuf[idx];
    if (i >= 6 && i <= 9) v += memout[(tok*4 + (i-6))*HDH + d];
    out[idx] = v * hw[tok*NHEADS + i];
}

// ------------------------------------------------------------ GLU elementwise
__global__ void __launch_bounds__(256) glu_kernel(
    const float* __restrict__ big, float* __restrict__ out, int N)
{
    long idx = (long)blockIdx.x*256 + threadIdx.x;
    if (idx >= (long)NT*N) return;
    long m = idx / N; int n = (int)(idx % N);
    float c = big[m*2L*N + n];
    float g = big[m*2L*N + N + n];
    out[idx] = c * sigf(g);
}

// ------------------------------------------------------------ memory write-gate
__global__ void __launch_bounds__(128) memgate_kernel(
    const float* __restrict__ xh, const float* __restrict__ wg,
    const float* __restrict__ bg, float* __restrict__ g)
{
    __shared__ float red[128];
    int t = blockIdx.x, tid = threadIdx.x;
    for (int h = 0; h < 4; h++){
        float v = xh[(size_t)t*HDIM + (6+h)*HDH + tid] * wg[h*HDH + tid];
        red[tid] = v; __syncthreads();
        for (int s = 64; s > 0; s >>= 1){ if (tid < s) red[tid] += red[tid+s]; __syncthreads(); }
        if (tid == 0) g[t*4 + h] = sigf(red[0] + bg[h]);
        __syncthreads();
    }
}

// ------------------------------------------------------------ memory scan
// One block per (batch, head, 8-column tile of M). 32 sequential chunks.
#define SCAN_SMEM ((64*QS*2 + 64*MT + 64 + 128*(MT+1) + 4)*4)
__global__ void __launch_bounds__(256) memscan_kernel(
    const float* __restrict__ q, const float* __restrict__ k,
    const float* __restrict__ v, const float* __restrict__ g,
    float* __restrict__ reads)
{
    extern __shared__ float smem[];
    float* sQ  = smem;                 // [64][QS]
    float* sK  = sQ + 64*QS;           // k*g, [64][QS]
    float* sV  = sK + 64*QS;           // [64][MT]
    float* sG  = sV + 64*MT;           // [64]
    float* sM  = sG + 64;              // [128][MT+1]
    float* sDec= sM + 128*(MT+1);
    int tid  = threadIdx.x;
    int mblk = blockIdx.x & 15;
    int h    = (blockIdx.x >> 4) & 3;
    int b    = blockIdx.x >> 6;
    int m0   = mblk * MT;
    for (int i = tid; i < 128*(MT+1); i += 256) sM[i] = 0.f;
    for (int c = 0; c < NCHUNK; c++){
        int tok0 = b*SL + c*CHUNK;
        __syncthreads();                               // prev update done
        if (tid < 64) sG[tid] = g[(tok0 + tid)*4 + h];
        __syncthreads();
        #pragma unroll
        for (int it = 0; it < 8; it++){
            int li = tid + it*256;
            int s  = li >> 5;
            int e4 = (li & 31) << 2;
            size_t gi = ((size_t)(tok0 + s)*4 + h)*HDH + e4;
            float4 qa = *(const float4*)(q + gi);
            float4 ka = *(const float4*)(k + gi);
            float gs = sG[s];
            int so = s*QS + e4;
            sQ[so] = qa.x; sQ[so+1] = qa.y; sQ[so+2] = qa.z; sQ[so+3] = qa.w;
            sK[so] = ka.x*gs; sK[so+1] = ka.y*gs; sK[so+2] = ka.z*gs; sK[so+3] = ka.w*gs;
        }
        if (tid < 128){
            int s = tid >> 1; int mm = (tid & 1)*4;
            float4 va = *(const float4*)(v + ((size_t)(tok0 + s)*4 + h)*HDH + m0 + mm);
            float* dv = &sV[s*MT + mm];
            dv[0]=va.x; dv[1]=va.y; dv[2]=va.z; dv[3]=va.w;
        }
        __syncthreads();
        if (tid < 32){
            float dsum = sG[tid] + sG[tid + 32];
            #pragma unroll
            for (int o = 16; o; o >>= 1) dsum += __shfl_down_sync(0xffffffffu, dsum, o);
            if (tid == 0) sDec[0] = 1.f - dsum*(1.f/64.f);
        }
        // reads = q @ M (pre-update M): thread -> (s, 2 cols)
        {
            int s  = tid & 63;
            int mi = (tid >> 6)*2;
            float a0 = 0.f, a1 = 0.f;
            const float* qr = sQ + s*QS;
            #pragma unroll 8
            for (int d = 0; d < HDH; d++){
                float qv = qr[d];
                a0 += qv * sM[d*(MT+1) + mi];
                a1 += qv * sM[d*(MT+1) + mi + 1];
            }
            size_t ro = ((size_t)(tok0 + s)*4 + h)*HDH + m0 + mi;
            reads[ro] = a0; reads[ro+1] = a1;
        }
        __syncthreads();                               // reads done before M update
        // M = decay*M + (k*g)^T v : thread -> (d, 4 cols)
        {
            int d  = tid & 127;
            int mb = (tid >> 7)*4;
            float dec = sDec[0];
            float a0 = dec*sM[d*(MT+1)+mb+0];
            float a1 = dec*sM[d*(MT+1)+mb+1];
            float a2 = dec*sM[d*(MT+1)+mb+2];
            float a3 = dec*sM[d*(MT+1)+mb+3];
            #pragma unroll 8
            for (int s = 0; s < 64; s++){
                float kgv = sK[s*QS + d];
                const float* vr = sV + s*MT + mb;
                a0 += kgv*vr[0]; a1 += kgv*vr[1]; a2 += kgv*vr[2]; a3 += kgv*vr[3];
            }
            sM[d*(MT+1)+mb+0]=a0; sM[d*(MT+1)+mb+1]=a1;
            sM[d*(MT+1)+mb+2]=a2; sM[d*(MT+1)+mb+3]=a3;
        }
    }
}

// ------------------------------------------------------------ SGEMM  C = A @ W^T (+epi)
// epi 0: C = acc (+bias)
// epi 1: C = resid + gate[row]*(acc (+bias))
// epi 2: C = A[row,col] * sigmoid(acc + bias)
__global__ void __launch_bounds__(256) sgemm_kernel(
    const float* __restrict__ A, int lda,
    const float* __restrict__ W, int ldw,
    float* C, int ldc, int K, int epi,
    const float* __restrict__ bias,
    const float* resid, const float* __restrict__ gate)
{
    __shared__ float As[16][128];
    __shared__ float Bs[16][128];
    int tid = threadIdx.x;
    int tx = tid & 15, ty = tid >> 4;
    long bm = (long)blockIdx.y * 128;
    long bn = (long)blockIdx.x * 128;
    float acc[8][8];
    #pragma unroll
    for (int i = 0; i < 8; i++)
        #pragma unroll
        for (int j = 0; j < 8; j++) acc[i][j] = 0.f;
    int lr = tid >> 2;
    int lc = (tid & 3) << 2;
    const float* Ap = A + (bm + lr)*(long)lda + lc;
    const float* Wp = W + (bn + lr)*(long)ldw + lc;
    for (int k0 = 0; k0 < K; k0 += 16){
        float4 a0 = *(const float4*)(Ap);
        float4 a1 = *(const float4*)(Ap + 64L*lda);
        float4 b0 = *(const float4*)(Wp);
        float4 b1 = *(const float4*)(Wp + 64L*ldw);
        As[lc+0][lr] = a0.x; As[lc+1][lr] = a0.y; As[lc+2][lr] = a0.z; As[lc+3][lr] = a0.w;
        As[lc+0][lr+64] = a1.x; As[lc+1][lr+64] = a1.y; As[lc+2][lr+64] = a1.z; As[lc+3][lr+64] = a1.w;
        Bs[lc+0][lr] = b0.x; Bs[lc+1][lr] = b0.y; Bs[lc+2][lr] = b0.z; Bs[lc+3][lr] = b0.w;
        Bs[lc+0][lr+64] = b1.x; Bs[lc+1][lr+64] = b1.y; Bs[lc+2][lr+64] = b1.z; Bs[lc+3][lr+64] = b1.w;
        __syncthreads();
        #pragma unroll
        for (int kk = 0; kk < 16; kk++){
            float ar[8], br[8];
            *(float4*)&ar[0] = *(const float4*)&As[kk][ty*8];
            *(float4*)&ar[4] = *(const float4*)&As[kk][ty*8+4];
            *(float4*)&br[0] = *(const float4*)&Bs[kk][tx*8];
            *(float4*)&br[4] = *(const float4*)&Bs[kk][tx*8+4];
            #pragma unroll
            for (int i = 0; i < 8; i++)
                #pragma unroll
                for (int j = 0; j < 8; j++) acc[i][j] += ar[i]*br[j];
        }
        __syncthreads();
        Ap += 16; Wp += 16;
    }
    long row0 = bm + ty*8, col0 = bn + tx*8;
    #pragma unroll
    for (int i = 0; i < 8; i++){
        long r = row0 + i;
        #pragma unroll
        for (int j = 0; j < 8; j++){
            long c = col0 + j;
            float v = acc[i][j];
            if (bias) v += bias[c];
            if (epi == 1)      v = resid[r*ldc + c] + gate[r]*v;
            else if (epi == 2) v = A[r*(long)lda + c] * sigf(v);
            C[r*ldc + c] = v;
        }
    }
}

// ------------------------------------------------------------ host side
static float* F(const void* sym){
    void* p = nullptr;
    cudaGetSymbolAddress(&p, sym);
    return (float*)p;
}

static void gemm(const float* A, int lda, const float* W, int ldw, float* C, int ldc,
                 int M, int N, int K, int epi,
                 const float* bias, const float* resid, const float* gate)
{
    dim3 g(N/128, M/128);
    sgemm_kernel<<<g, 256>>>(A, lda, W, ldw, C, ldc, K, epi, bias, resid, gate);
}

extern "C" void kernel_launch(void* const* d_in, const int* in_sizes, int n_in,
                              void* d_out, int out_size)
{
    const float* x            = (const float*)d_in[0];
    const float* norm1_w      = (const float*)d_in[1];
    const float* norm2_w      = (const float*)d_in[2];
    const float* norm3_w      = (const float*)d_in[3];
    const float* convstack_w  = (const float*)d_in[4];
    const float* convstack_b  = (const float*)d_in[5];
    const float* conv_proj_w  = (const float*)d_in[6];
    const float* conv_proj_b  = (const float*)d_in[7];
    const float* gate_proj_w  = (const float*)d_in[8];
    const float* head_router_w= (const float*)d_in[9];
    const float* head_router_b= (const float*)d_in[10];
    const float* head_conv_w  = (const float*)d_in[11];
    const float* head_conv_b  = (const float*)d_in[12];
    const float* mem_Wq       = (const float*)d_in[13];
    const float* mem_Wk       = (const float*)d_in[14];
    const float* mem_Wv       = (const float*)d_in[15];
    const float* mem_Wg_w     = (const float*)d_in[16];
    const float* mem_Wg_b     = (const float*)d_in[17];
    const float* mem_Wout     = (const float*)d_in[18];
    const float* mix_gate_w   = (const float*)d_in[19];
    const float* mix_gate_b   = (const float*)d_in[20];
    const float* mixing_w     = (const float*)d_in[21];
    const float* mixing_b     = (const float*)d_in[22];
    const float* ffn_in_w     = (const float*)d_in[23];
    const float* ffn_out_w    = (const float*)d_in[24];
    const float* conv_gate_w  = (const float*)d_in[25];
    const float* conv_gate_b  = (const float*)d_in[26];
    const float* state_gate_w = (const float*)d_in[27];
    const float* state_gate_b = (const float*)d_in[28];
    const float* ffn_gate_w   = (const float*)d_in[29];
    const float* ffn_gate_b   = (const float*)d_in[30];
    float* out = (float*)d_out;

    float* y    = F(g_y);
    float* t0   = F(g_t0);
    float* t1   = F(g_t1);
    float* xh   = F(g_xh);
    float* h2   = F(g_h2);
    float* big  = F(g_big);
    float* ffn  = F(g_ffn);
    float* qb   = F(g_q);
    float* kb   = F(g_k);
    float* vb   = F(g_v);
    float* rd   = F(g_rd);
    float* mo   = F(g_mo);
    float* gm   = F(g_gm);
    float* hw   = F(g_hw);
    float* gate = F(g_gate);

    cudaFuncSetAttribute(memscan_kernel,
                         cudaFuncAttributeMaxDynamicSharedMemorySize, SCAN_SMEM);

    const int EW = (NT*HDIM + 255)/256;
    static const int stack_dils[6] = {1,2,4,8,16,32};

    // ============ stage A: conv branch ============
    rms_router_kernel<<<NT,256>>>(x, norm1_w, conv_gate_w, conv_gate_b,
                                  y, gate, nullptr, nullptr, nullptr);
    const float* cin = y;
    float* pp[2] = {t0, t1};
    for (int j = 0; j < 6; j++){
        convstack_kernel<<<EW,256>>>(cin, pp[j&1],
                                     convstack_w + (size_t)j*HDIM*KW,
                                     convstack_b + (size_t)j*HDIM, stack_dils[j]);
        cin = pp[j&1];
    }
    gemm(cin, HDIM, conv_proj_w, HDIM, out, HDIM, NT, HDIM, HDIM, 1,
         conv_proj_b, x, gate);

    // ============ stage B: state branch ============
    rms_router_kernel<<<NT,256>>>(out, norm2_w, state_gate_w, state_gate_b,
                                  y, gate, head_router_w, head_router_b, hw);
    gemm(y, HDIM, gate_proj_w, HDIM, big, 2*HDIM, NT, 2*HDIM, HDIM, 0,
         nullptr, nullptr, nullptr);
    glu_kernel<<<EW,256>>>(big, xh, HDIM);
    memgate_kernel<<<NT,128>>>(xh, mem_Wg_w, mem_Wg_b, gm);
    for (int h = 0; h < 4; h++){
        gemm(xh + (6+h)*HDH, HDIM, mem_Wq + (size_t)h*HDH*HDH, HDH,
             qb + h*HDH, 4*HDH, NT, HDH, HDH, 0, nullptr, nullptr, nullptr);
        gemm(xh + (6+h)*HDH, HDIM, mem_Wk + (size_t)h*HDH*HDH, HDH,
             kb + h*HDH, 4*HDH, NT, HDH, HDH, 0, nullptr, nullptr, nullptr);
        gemm(xh + (6+h)*HDH, HDIM, mem_Wv + (size_t)h*MEMD*HDH, HDH,
             vb + h*HDH, 4*HDH, NT, MEMD, HDH, 0, nullptr, nullptr, nullptr);
    }
    memscan_kernel<<<BB*4*(MEMD/MT), 256, SCAN_SMEM>>>(qb, kb, vb, gm, rd);
    for (int h = 0; h < 4; h++){
        gemm(rd + h*HDH, 4*HDH, mem_Wout + (size_t)h*HDH*MEMD, MEMD,
             mo + h*HDH, 4*HDH, NT, HDH, MEMD, 0, nullptr, nullptr, nullptr);
    }
    headconv_kernel<<<EW,256>>>(xh, h2, head_conv_w, head_conv_b, 0);
    headconv_kernel<<<EW,256>>>(h2, xh, head_conv_w, head_conv_b, 1);
    headconv_kernel<<<EW,256>>>(xh, h2, head_conv_w, head_conv_b, 2);
    combine_kernel<<<EW,256>>>(h2, mo, hw, t0);
    gemm(t0, HDIM, mix_gate_w, HDIM, t1, HDIM, NT, HDIM, HDIM, 2,
         mix_gate_b, nullptr, nullptr);
    gemm(t1, HDIM, mixing_w, HDIM, out, HDIM, NT, HDIM, HDIM, 1,
         mixing_b, out, gate);

    // ============ stage C: FFN ============
    rms_router_kernel<<<NT,256>>>(out, norm3_w, ffn_gate_w, ffn_gate_b,
                                  y, gate, nullptr, nullptr, nullptr);
    gemm(y, HDIM, ffn_in_w, HDIM, big, 2*INNERD, NT, 2*INNERD, HDIM, 0,
         nullptr, nullptr, nullptr);
    glu_kernel<<<(NT*INNERD + 255)/256, 256>>>(big, ffn, INNERD);
    gemm(ffn, INNERD, ffn_out_w, INNERD, out, HDIM, NT, HDIM, INNERD, 1,
         nullptr, out, gate);
}

// round 4
// speedup vs baseline: 1.7018x; 1.7018x over previous
#include <cuda_runtime.h>
#include <math.h>
#include <stdint.h>

#define HDIM   1536
#define BB     4
#define SL     2048
#define NHEADS 12
#define HDH    128
#define MEMD   128
#define INNERD 6144
#define NT     (BB*SL)
#define KW     4
#define CHUNK  64
#define NCHUNK (SL/CHUNK)
#define MT     8
#define QS     129
#define BM     128
#define BN     128
#define BKK    16

// ------------------------------------------------------------------ scratch
__device__ float g_y   [(size_t)NT*HDIM];
__device__ float g_t0  [(size_t)NT*HDIM];
__device__ float g_t1  [(size_t)NT*HDIM];
__device__ float g_xh  [(size_t)NT*HDIM];
__device__ float g_h2  [(size_t)NT*HDIM];
__device__ float g_big [(size_t)NT*2*INNERD];
__device__ float g_ffn [(size_t)NT*INNERD];
__device__ float g_q   [(size_t)NT*4*HDH];
__device__ float g_k   [(size_t)NT*4*HDH];
__device__ float g_v   [(size_t)NT*4*HDH];
__device__ float g_rd  [(size_t)NT*4*HDH];
__device__ float g_mo  [(size_t)NT*4*HDH];
__device__ float g_gm  [(size_t)NT*4];
__device__ float g_hw  [(size_t)NT*NHEADS];
__device__ float g_gate[NT];
__device__ float g_wr  [40370176];   // tf32-rounded weights

__constant__ int c_dils[NHEADS][3] = {
    {1,2,4},{1,1,1},{4,8,16},{8,16,32},{32,64,128},{64,128,256},
    {256,512,1024},{1,100,200},{1,500,1000},{1,1024,2048},{3,9,27},{5,25,125}};

__device__ __forceinline__ float sigf(float v){ return 1.f/(1.f+expf(-v)); }
__device__ __forceinline__ float geluf(float v){ return 0.5f*v*(1.f+erff(v*0.70710678118654752f)); }
__device__ __forceinline__ float rtf(float v){
    float r; asm("cvt.rna.tf32.f32 %0, %1;" : "=f"(r) : "f"(v)); return r;
}

__device__ __forceinline__ void mma8(float* c, const uint32_t* a, const uint32_t* b){
    asm volatile("mma.sync.aligned.m16n8k8.row.col.f32.tf32.tf32.f32 "
        "{%0,%1,%2,%3}, {%4,%5,%6,%7}, {%8,%9}, {%0,%1,%2,%3};"
        : "+f"(c[0]), "+f"(c[1]), "+f"(c[2]), "+f"(c[3])
        : "r"(a[0]), "r"(a[1]), "r"(a[2]), "r"(a[3]),
          "r"(b[0]), "r"(b[1]));
}

// ============================================================ tf32 mma GEMM
// C[M,N] = A[M,K] @ W[N,K]^T   (K-major fp32, pre-rounded to tf32)
// epi 0: acc(+bias)
// epi 1: resid + gate[row]*(acc+bias)
// epi 2: A[row,col]*sigmoid(acc+bias)
__global__ void __launch_bounds__(256)
mma_gemm_kernel(const float* __restrict__ A, long lda, long aZ,
                const float* __restrict__ W, long ldw, long wZ,
                float* __restrict__ C, long ldc, long cZ,
                int K, int epi, int rnd,
                const float* __restrict__ bias,
                const float* __restrict__ resid,
                const float* __restrict__ gate)
{
    __shared__ float As[2][BKK][BM+8];
    __shared__ float Bs[2][BKK][BN+8];
    int tid = threadIdx.x, lane = tid & 31, warp = tid >> 5;
    int wm = warp & 1, wn = warp >> 1;
    int r = lane >> 2, cl = lane & 3;
    long bm = (long)blockIdx.y*BM, bn = (long)blockIdx.x*BN;
    A += (long)blockIdx.z*aZ;
    W += (long)blockIdx.z*wZ;
    C += (long)blockIdx.z*cZ;
    const float* Rz = resid ? resid + (long)blockIdx.z*cZ : (const float*)0;

    float acc[4][4][4];
    #pragma unroll
    for (int i=0;i<4;i++)
        #pragma unroll
        for (int j=0;j<4;j++)
            #pragma unroll
            for (int q=0;q<4;q++) acc[i][j][q]=0.f;

    int lm = tid & 127;
    int kq = tid >> 7;                       // 0 or 1
    const float* Ab = A + (bm + lm)*lda + kq*4;
    const float* Wb = W + (bn + lm)*ldw + kq*4;

    const int iters = K >> 4;
    {   // prologue: stage k-tile 0 into buffer 0
        float4 a0 = *(const float4*)(Ab);
        float4 a1 = *(const float4*)(Ab + 8);
        float4 b0 = *(const float4*)(Wb);
        float4 b1 = *(const float4*)(Wb + 8);
        #pragma unroll
        for (int j=0;j<4;j++){
            As[0][kq*4+j][lm]   = ((const float*)&a0)[j];
            As[0][kq*4+8+j][lm] = ((const float*)&a1)[j];
            Bs[0][kq*4+j][lm]   = ((const float*)&b0)[j];
            Bs[0][kq*4+8+j][lm] = ((const float*)&b1)[j];
        }
    }
    __syncthreads();

    for (int i = 0; i < iters; i++){
        int bsel = i & 1;
        float4 a0, a1, b0, b1;
        if (i+1 < iters){
            const float* Ap = Ab + (long)(i+1)*16;
            const float* Wp = Wb + (long)(i+1)*16;
            a0 = *(const float4*)(Ap);  a1 = *(const float4*)(Ap + 8);
            b0 = *(const float4*)(Wp);  b1 = *(const float4*)(Wp + 8);
        }
        #pragma unroll
        for (int kk = 0; kk < 2; kk++){
            int kb = kk*8;
            uint32_t af[4][4], bf[4][2];
            #pragma unroll
            for (int mt=0;mt<4;mt++){
                int m0 = wm*64 + mt*16;
                af[mt][0] = __float_as_uint(As[bsel][kb+cl  ][m0+r  ]);
                af[mt][1] = __float_as_uint(As[bsel][kb+cl  ][m0+r+8]);
                af[mt][2] = __float_as_uint(As[bsel][kb+cl+4][m0+r  ]);
                af[mt][3] = __float_as_uint(As[bsel][kb+cl+4][m0+r+8]);
            }
            #pragma unroll
            for (int nt=0;nt<4;nt++){
                int n0 = wn*32 + nt*8;
                bf[nt][0] = __float_as_uint(Bs[bsel][kb+cl  ][n0+r]);
                bf[nt][1] = __float_as_uint(Bs[bsel][kb+cl+4][n0+r]);
            }
            #pragma unroll
            for (int mt=0;mt<4;mt++)
                #pragma unroll
                for (int nt=0;nt<4;nt++)
                    mma8(acc[mt][nt], af[mt], bf[nt]);
        }
        if (i+1 < iters){
            __syncthreads();
            int nb = (i+1)&1;
            #pragma unroll
            for (int j=0;j<4;j++){
                As[nb][kq*4+j][lm]   = ((const float*)&a0)[j];
                As[nb][kq*4+8+j][lm] = ((const float*)&a1)[j];
                Bs[nb][kq*4+j][lm]   = ((const float*)&b0)[j];
                Bs[nb][kq*4+8+j][lm] = ((const float*)&b1)[j];
            }
            __syncthreads();
        }
    }

    // ---------------- epilogue (register -> global, float2 stores)
    #pragma unroll
    for (int mt=0;mt<4;mt++){
        #pragma unroll
        for (int nt=0;nt<4;nt++){
            long row0 = bm + wm*64 + mt*16 + r;
            long col  = bn + wn*32 + nt*8 + 2*cl;
            #pragma unroll
            for (int hh=0;hh<2;hh++){
                long row = row0 + hh*8;
                float v0 = acc[mt][nt][hh*2+0];
                float v1 = acc[mt][nt][hh*2+1];
                if (bias){ v0 += bias[col]; v1 += bias[col+1]; }
                if (epi == 1){
                    float g = gate[row];
                    v0 = Rz[row*ldc + col]   + g*v0;
                    v1 = Rz[row*ldc + col+1] + g*v1;
                } else if (epi == 2){
                    v0 = A[row*lda + col]   * sigf(v0);
                    v1 = A[row*lda + col+1] * sigf(v1);
                }
                if (rnd){ v0 = rtf(v0); v1 = rtf(v1); }
                float2 o; o.x = v0; o.y = v1;
                *(float2*)(C + row*ldc + col) = o;
            }
        }
    }
}

// ------------------------------------------------------------ weight rounding
__global__ void __launch_bounds__(256) roundw_kernel(
    const float4* __restrict__ in, float4* __restrict__ out, int n4)
{
    int i = blockIdx.x*256 + threadIdx.x;
    if (i < n4){
        float4 v = in[i];
        v.x = rtf(v.x); v.y = rtf(v.y); v.z = rtf(v.z); v.w = rtf(v.w);
        out[i] = v;
    }
}

// ------------------------------------------------------------ rms + gate (+router)
__global__ void __launch_bounds__(256) rms_router_kernel(
    const float* __restrict__ x, const float* __restrict__ nw,
    const float* __restrict__ gw, const float* __restrict__ gb,
    float* __restrict__ y, float* __restrict__ gate,
    const float* __restrict__ rw, const float* __restrict__ rb,
    float* __restrict__ hw, int doRound)
{
    __shared__ float sy[HDIM];
    __shared__ float red[256];
    int t = blockIdx.x, tid = threadIdx.x;
    const float* xr = x + (size_t)t*HDIM;
    float ss = 0.f, gd = 0.f;
    for (int i = tid; i < HDIM; i += 256){
        float v = xr[i]; sy[i] = v; ss += v*v; gd += v*gw[i];
    }
    red[tid] = ss; __syncthreads();
    for (int s = 128; s > 0; s >>= 1){ if (tid < s) red[tid] += red[tid+s]; __syncthreads(); }
    float rs = rsqrtf(red[0]*(1.f/HDIM) + 1e-6f);
    __syncthreads();
    red[tid] = gd; __syncthreads();
    for (int s = 128; s > 0; s >>= 1){ if (tid < s) red[tid] += red[tid+s]; __syncthreads(); }
    if (tid == 0) gate[t] = sigf(red[0] + gb[0]);
    float* yr = y + (size_t)t*HDIM;
    for (int i = tid; i < HDIM; i += 256){
        float v = sy[i]*rs*nw[i];
        yr[i] = doRound ? rtf(v) : v;
        sy[i] = v;
    }
    if (rw){
        __syncthreads();
        int warp = tid >> 5, lane = tid & 31;
        for (int r = warp; r < NHEADS; r += 8){
            float s = 0.f;
            for (int i = lane; i < HDIM; i += 32) s += sy[i]*rw[r*HDIM + i];
            #pragma unroll
            for (int o = 16; o; o >>= 1) s += __shfl_down_sync(0xffffffffu, s, o);
            if (lane == 0) hw[(size_t)t*NHEADS + r] = sigf(s + rb[r]);
        }
    }
}

// ------------------------------------------------------------ conv stack (float4)
__global__ void __launch_bounds__(256) convstack_v4(
    const float4* __restrict__ in, float4* __restrict__ out,
    const float* __restrict__ w, const float* __restrict__ b, int dil, int doRound)
{
    const int C4 = HDIM/4;
    int idx = blockIdx.x*256 + threadIdx.x;
    int c4 = idx % C4;
    int tok = idx / C4;
    int t = tok & (SL-1);
    int c = c4*4;
    float4 acc = *(const float4*)(b + c);
    float4 xv = in[idx];
    #pragma unroll
    for (int k = 0; k < KW-1; k++){
        int tt = t - (KW-1-k)*dil;
        if (tt >= 0){
            float4 iv = in[idx + (tt - t)*C4];
            acc.x += iv.x * w[(c+0)*KW + k];
            acc.y += iv.y * w[(c+1)*KW + k];
            acc.z += iv.z * w[(c+2)*KW + k];
            acc.w += iv.w * w[(c+3)*KW + k];
        }
    }
    acc.x += xv.x * w[(c+0)*KW + 3];
    acc.y += xv.y * w[(c+1)*KW + 3];
    acc.z += xv.z * w[(c+2)*KW + 3];
    acc.w += xv.w * w[(c+3)*KW + 3];
    float4 o;
    o.x = xv.x + geluf(acc.x); o.y = xv.y + geluf(acc.y);
    o.z = xv.z + geluf(acc.z); o.w = xv.w + geluf(acc.w);
    if (doRound){ o.x=rtf(o.x); o.y=rtf(o.y); o.z=rtf(o.z); o.w=rtf(o.w); }
    out[idx] = o;
}

// ------------------------------------------------------------ per-head conv (float4)
__global__ void __launch_bounds__(256) headconv_v4(
    const float4* __restrict__ in, float4* __restrict__ out,
    const float* __restrict__ w, const float* __restrict__ b, int stage)
{
    const int C4 = HDIM/4;
    int idx = blockIdx.x*256 + threadIdx.x;
    int c4 = idx % C4;
    int tok = idx / C4;
    int t = tok & (SL-1);
    int head = c4 >> 5;
    int d = (c4 & 31)*4;
    int dil = c_dils[head][stage];
    int wb = (head*3 + stage)*HDH + d;
    float4 acc = *(const float4*)(b + wb);
    float4 xv = in[idx];
    #pragma unroll
    for (int k = 0; k < KW-1; k++){
        int tt = t - (KW-1-k)*dil;
        if (tt >= 0){
            float4 iv = in[idx + (tt - t)*C4];
            acc.x += iv.x * w[(wb+0)*KW + k];
            acc.y += iv.y * w[(wb+1)*KW + k];
            acc.z += iv.z * w[(wb+2)*KW + k];
            acc.w += iv.w * w[(wb+3)*KW + k];
        }
    }
    acc.x += xv.x * w[(wb+0)*KW + 3];
    acc.y += xv.y * w[(wb+1)*KW + 3];
    acc.z += xv.z * w[(wb+2)*KW + 3];
    acc.w += xv.w * w[(wb+3)*KW + 3];
    float4 o; o.x = xv.x + acc.x; o.y = xv.y + acc.y; o.z = xv.z + acc.z; o.w = xv.w + acc.w;
    out[idx] = o;
}

// ------------------------------------------------------------ combine heads (float4)
__global__ void __launch_bounds__(256) combine_v4(
    const float4* __restrict__ hbuf, const float4* __restrict__ memout,
    const float* __restrict__ hw, float4* __restrict__ out)
{
    const int C4 = HDIM/4;
    int idx = blockIdx.x*256 + threadIdx.x;
    int c4 = idx % C4;
    long tok = idx / C4;
    int head = c4 >> 5;
    float4 v = hbuf[idx];
    if (head >= 6 && head <= 9){
        float4 mv = memout[tok*128 + (head-6)*32 + (c4 & 31)];
        v.x += mv.x; v.y += mv.y; v.z += mv.z; v.w += mv.w;
    }
    float g = hw[tok*NHEADS + head];
    float4 o;
    o.x = rtf(v.x*g); o.y = rtf(v.y*g); o.z = rtf(v.z*g); o.w = rtf(v.w*g);
    out[idx] = o;
}

// ------------------------------------------------------------ GLU (float4)
__global__ void __launch_bounds__(256) glu_v4(
    const float4* __restrict__ big, float4* __restrict__ out, int N4)
{
    long idx = (long)blockIdx.x*256 + threadIdx.x;
    if (idx >= (long)NT*N4) return;
    long m = idx / N4; int n = (int)(idx % N4);
    float4 c = big[m*2*N4 + n];
    float4 g = big[m*2*N4 + N4 + n];
    float4 o;
    o.x = rtf(c.x*sigf(g.x)); o.y = rtf(c.y*sigf(g.y));
    o.z = rtf(c.z*sigf(g.z)); o.w = rtf(c.w*sigf(g.w));
    out[idx] = o;
}

// ------------------------------------------------------------ memory write-gate
__global__ void __launch_bounds__(128) memgate_kernel(
    const float* __restrict__ xh, const float* __restrict__ wg,
    const float* __restrict__ bg, float* __restrict__ g)
{
    __shared__ float red[128];
    int t = blockIdx.x, tid = threadIdx.x;
    for (int h = 0; h < 4; h++){
        float v = xh[(size_t)t*HDIM + (6+h)*HDH + tid] * wg[h*HDH + tid];
        red[tid] = v; __syncthreads();
        for (int s = 64; s > 0; s >>= 1){ if (tid < s) red[tid] += red[tid+s]; __syncthreads(); }
        if (tid == 0) g[t*4 + h] = sigf(red[0] + bg[h]);
        __syncthreads();
    }
}

// ------------------------------------------------------------ memory scan
#define SCAN_SMEM ((64*QS*2 + 64*MT + 64 + 128*(MT+1) + 4)*4)
__global__ void __launch_bounds__(256) memscan_kernel(
    const float* __restrict__ q, const float* __restrict__ k,
    const float* __restrict__ v, const float* __restrict__ g,
    float* __restrict__ reads)
{
    extern __shared__ float smem[];
    float* sQ  = smem;
    float* sK  = sQ + 64*QS;
    float* sV  = sK + 64*QS;
    float* sG  = sV + 64*MT;
    float* sM  = sG + 64;
    float* sDec= sM + 128*(MT+1);
    int tid  = threadIdx.x;
    int mblk = blockIdx.x & 15;
    int h    = (blockIdx.x >> 4) & 3;
    int b    = blockIdx.x >> 6;
    int m0   = mblk * MT;
    for (int i = tid; i < 128*(MT+1); i += 256) sM[i] = 0.f;
    for (int c = 0; c < NCHUNK; c++){
        int tok0 = b*SL + c*CHUNK;
        __syncthreads();
        if (tid < 64) sG[tid] = g[(tok0 + tid)*4 + h];
        __syncthreads();
        #pragma unroll
        for (int it = 0; it < 8; it++){
            int li = tid + it*256;
            int s  = li >> 5;
            int e4 = (li & 31) << 2;
            size_t gi = ((size_t)(tok0 + s)*4 + h)*HDH + e4;
            float4 qa = *(const float4*)(q + gi);
            float4 ka = *(const float4*)(k + gi);
            float gs = sG[s];
            int so = s*QS + e4;
            sQ[so] = qa.x; sQ[so+1] = qa.y; sQ[so+2] = qa.z; sQ[so+3] = qa.w;
            sK[so] = ka.x*gs; sK[so+1] = ka.y*gs; sK[so+2] = ka.z*gs; sK[so+3] = ka.w*gs;
        }
        if (tid < 128){
            int s = tid >> 1; int mm = (tid & 1)*4;
            float4 va = *(const float4*)(v + ((size_t)(tok0 + s)*4 + h)*HDH + m0 + mm);
            float* dv = &sV[s*MT + mm];
            dv[0]=va.x; dv[1]=va.y; dv[2]=va.z; dv[3]=va.w;
        }
        __syncthreads();
        if (tid < 32){
            float dsum = sG[tid] + sG[tid + 32];
            #pragma unroll
            for (int o = 16; o; o >>= 1) dsum += __shfl_down_sync(0xffffffffu, dsum, o);
            if (tid == 0) sDec[0] = 1.f - dsum*(1.f/64.f);
        }
        {
            int s  = tid & 63;
            int mi = (tid >> 6)*2;
            float a0 = 0.f, a1 = 0.f;
            const float* qr = sQ + s*QS;
            #pragma unroll 8
            for (int d = 0; d < HDH; d++){
                float qv = qr[d];
                a0 += qv * sM[d*(MT+1) + mi];
                a1 += qv * sM[d*(MT+1) + mi + 1];
            }
            size_t ro = ((size_t)(tok0 + s)*4 + h)*HDH + m0 + mi;
            reads[ro] = rtf(a0); reads[ro+1] = rtf(a1);
        }
        __syncthreads();
        {
            int d  = tid & 127;
            int mb = (tid >> 7)*4;
            float dec = sDec[0];
            float a0 = dec*sM[d*(MT+1)+mb+0];
            float a1 = dec*sM[d*(MT+1)+mb+1];
            float a2 = dec*sM[d*(MT+1)+mb+2];
            float a3 = dec*sM[d*(MT+1)+mb+3];
            #pragma unroll 8
            for (int s = 0; s < 64; s++){
                float kgv = sK[s*QS + d];
                const float* vr = sV + s*MT + mb;
                a0 += kgv*vr[0]; a1 += kgv*vr[1]; a2 += kgv*vr[2]; a3 += kgv*vr[3];
            }
            sM[d*(MT+1)+mb+0]=a0; sM[d*(MT+1)+mb+1]=a1;
            sM[d*(MT+1)+mb+2]=a2; sM[d*(MT+1)+mb+3]=a3;
        }
    }
}

// ------------------------------------------------------------ host side
static float* F(const void* sym){
    void* p = nullptr;
    cudaGetSymbolAddress(&p, sym);
    return (float*)p;
}

static void gemmBig(const float* A, const float* W, float* C,
                    long lda, long ldw, long ldc, int M, int N, int K,
                    int epi, int rnd, const float* bias,
                    const float* resid, const float* gate)
{
    dim3 g(N/BN, M/BM, 1);
    mma_gemm_kernel<<<g, 256>>>(A, lda, 0, W, ldw, 0, C, ldc, 0,
                                K, epi, rnd, bias, resid, gate);
}
static void gemmMem(const float* A, long lda, long aZ,
                    const float* W, float* C, long cZ)
{
    dim3 g(1, NT/BM, 4);
    mma_gemm_kernel<<<g, 256>>>(A, lda, aZ, W, 128, 16384,
                                C, 512, cZ, 128, 0, 0,
                                nullptr, nullptr, nullptr);
}
static void roundw(const float* in, float* out, size_t n){
    int n4 = (int)(n/4);
    roundw_kernel<<<(n4 + 255)/256, 256>>>((const float4*)in, (float4*)out, n4);
}

extern "C" void kernel_launch(void* const* d_in, const int* in_sizes, int n_in,
                              void* d_out, int out_size)
{
    const float* x            = (const float*)d_in[0];
    const float* norm1_w      = (const float*)d_in[1];
    const float* norm2_w      = (const float*)d_in[2];
    const float* norm3_w      = (const float*)d_in[3];
    const float* convstack_w  = (const float*)d_in[4];
    const float* convstack_b  = (const float*)d_in[5];
    const float* conv_proj_w  = (const float*)d_in[6];
    const float* conv_proj_b  = (const float*)d_in[7];
    const float* gate_proj_w  = (const float*)d_in[8];
    const float* head_router_w= (const float*)d_in[9];
    const float* head_router_b= (const float*)d_in[10];
    const float* head_conv_w  = (const float*)d_in[11];
    const float* head_conv_b  = (const float*)d_in[12];
    const float* mem_Wq       = (const float*)d_in[13];
    const float* mem_Wk       = (const float*)d_in[14];
    const float* mem_Wv       = (const float*)d_in[15];
    const float* mem_Wg_w     = (const float*)d_in[16];
    const float* mem_Wg_b     = (const float*)d_in[17];
    const float* mem_Wout     = (const float*)d_in[18];
    const float* mix_gate_w   = (const float*)d_in[19];
    const float* mix_gate_b   = (const float*)d_in[20];
    const float* mixing_w     = (const float*)d_in[21];
    const float* mixing_b     = (const float*)d_in[22];
    const float* ffn_in_w     = (const float*)d_in[23];
    const float* ffn_out_w    = (const float*)d_in[24];
    const float* conv_gate_w  = (const float*)d_in[25];
    const float* conv_gate_b  = (const float*)d_in[26];
    const float* state_gate_w = (const float*)d_in[27];
    const float* state_gate_b = (const float*)d_in[28];
    const float* ffn_gate_w   = (const float*)d_in[29];
    const float* ffn_gate_b   = (const float*)d_in[30];
    float* out = (float*)d_out;

    float* y    = F(g_y);
    float* t0   = F(g_t0);
    float* t1   = F(g_t1);
    float* xh   = F(g_xh);
    float* h2   = F(g_h2);
    float* big  = F(g_big);
    float* ffn  = F(g_ffn);
    float* qb   = F(g_q);
    float* kb   = F(g_k);
    float* vb   = F(g_v);
    float* rd   = F(g_rd);
    float* mo   = F(g_mo);
    float* gm   = F(g_gm);
    float* hw   = F(g_hw);
    float* gate = F(g_gate);
    float* wr   = F(g_wr);

    float* w_cp  = wr;                 // conv_proj   2359296
    float* w_gp  = wr + 2359296;       // gate_proj   4718592
    float* w_q   = wr + 7077888;       // mem Wq        65536
    float* w_k   = wr + 7143424;
    float* w_v   = wr + 7208960;
    float* w_o   = wr + 7274496;
    float* w_mg  = wr + 7340032;       // mix_gate    2359296
    float* w_mx  = wr + 9699328;       // mixing      2359296
    float* w_fi  = wr + 12058624;      // ffn_in     18874368
    float* w_fo  = wr + 30932992;      // ffn_out     9437184

    cudaFuncSetAttribute(memscan_kernel,
        cudaFuncAttributeMaxDynamicSharedMemorySize, SCAN_SMEM);

    roundw(conv_proj_w, w_cp, 2359296);
    roundw(gate_proj_w, w_gp, 4718592);
    roundw(mem_Wq, w_q, 65536);
    roundw(mem_Wk, w_k, 65536);
    roundw(mem_Wv, w_v, 65536);
    roundw(mem_Wout, w_o, 65536);
    roundw(mix_gate_w, w_mg, 2359296);
    roundw(mixing_w, w_mx, 2359296);
    roundw(ffn_in_w, w_fi, 18874368);
    roundw(ffn_out_w, w_fo, 9437184);

    const int EW4 = NT*HDIM/4/256;
    static const int stack_dils[6] = {1,2,4,8,16,32};

    // ============ stage A: conv branch ============
    rms_router_kernel<<<NT,256>>>(x, norm1_w, conv_gate_w, conv_gate_b,
                                  y, gate, nullptr, nullptr, nullptr, 0);
    const float* cin = y;
    float* pp[2] = {t0, t1};
    for (int j = 0; j < 6; j++){
        convstack_v4<<<EW4,256>>>((const float4*)cin, (float4*)pp[j&1],
                                  convstack_w + (size_t)j*HDIM*KW,
                                  convstack_b + (size_t)j*HDIM, stack_dils[j],
                                  (j == 5) ? 1 : 0);
        cin = pp[j&1];
    }
    gemmBig(cin, w_cp, out, HDIM, HDIM, HDIM, NT, HDIM, HDIM, 1, 0,
            conv_proj_b, x, gate);

    // ============ stage B: state branch ============
    rms_router_kernel<<<NT,256>>>(out, norm2_w, state_gate_w, state_gate_b,
                                  y, gate, head_router_w, head_router_b, hw, 1);
    gemmBig(y, w_gp, big, HDIM, HDIM, 2*HDIM, NT, 2*HDIM, HDIM, 0, 0,
            nullptr, nullptr, nullptr);
    glu_v4<<<EW4,256>>>((const float4*)big, (float4*)xh, HDIM/4);
    memgate_kernel<<<NT,128>>>(xh, mem_Wg_w, mem_Wg_b, gm);
    gemmMem(xh + 6*HDH, HDIM, HDH, w_q, qb, HDH);
    gemmMem(xh + 6*HDH, HDIM, HDH, w_k, kb, HDH);
    gemmMem(xh + 6*HDH, HDIM, HDH, w_v, vb, HDH);
    memscan_kernel<<<BB*4*(MEMD/MT), 256, SCAN_SMEM>>>(qb, kb, vb, gm, rd);
    gemmMem(rd, 512, HDH, w_o, mo, HDH);
    headconv_v4<<<EW4,256>>>((const float4*)xh, (float4*)h2, head_conv_w, head_conv_b, 0);
    headconv_v4<<<EW4,256>>>((const float4*)h2, (float4*)xh, head_conv_w, head_conv_b, 1);
    headconv_v4<<<EW4,256>>>((const float4*)xh, (float4*)h2, head_conv_w, head_conv_b, 2);
    combine_v4<<<EW4,256>>>((const float4*)h2, (const float4*)mo, hw, (float4*)t0);
    gemmBig(t0, w_mg, t1, HDIM, HDIM, HDIM, NT, HDIM, HDIM, 2, 1,
            mix_gate_b, nullptr, nullptr);
    gemmBig(t1, w_mx, out, HDIM, HDIM, HDIM, NT, HDIM, HDIM, 1, 0,
            mixing_b, out, gate);

    // ============ stage C: FFN ============
    rms_router_kernel<<<NT,256>>>(out, norm3_w, ffn_gate_w, ffn_gate_b,
                                  y, gate, nullptr, nullptr, nullptr, 1);
    gemmBig(y, w_fi, big, HDIM, HDIM, 2*INNERD, NT, 2*INNERD, HDIM, 0, 0,
            nullptr, nullptr, nullptr);
    glu_v4<<<(NT*INNERD/4 + 255)/256, 256>>>((const float4*)big, (float4*)ffn, INNERD/4);
    gemmBig(ffn, w_fo, out, INNERD, INNERD, HDIM, NT, HDIM, INNERD, 1, 0,
            nullptr, out, gate);
}

// round 5
// speedup vs baseline: 2.9651x; 1.7423x over previous
#include <cuda_runtime.h>
#include <math.h>
#include <stdint.h>

#define HDIM   1536
#define BB     4
#define SL     2048
#define NHEADS 12
#define HDH    128
#define MEMD   128
#define INNERD 6144
#define NT     (BB*SL)
#define KW     4
#define CHUNK  64
#define NCHUNK (SL/CHUNK)
#define MT     8
#define QS     129

// ------------------------------------------------------------------ scratch
__device__ float g_y   [(size_t)NT*HDIM];
__device__ float g_t0  [(size_t)NT*HDIM];
__device__ float g_t1  [(size_t)NT*HDIM];
__device__ float g_xh  [(size_t)NT*HDIM];
__device__ float g_h2  [(size_t)NT*HDIM];
__device__ float g_big [(size_t)NT*2*INNERD];
__device__ float g_ffn [(size_t)NT*INNERD];
__device__ float g_q   [(size_t)NT*4*HDH];
__device__ float g_k   [(size_t)NT*4*HDH];
__device__ float g_v   [(size_t)NT*4*HDH];
__device__ float g_rd  [(size_t)NT*4*HDH];
__device__ float g_mo  [(size_t)NT*4*HDH];
__device__ float g_gm  [(size_t)NT*4];
__device__ float g_hw  [(size_t)NT*NHEADS];
__device__ float g_gate[NT];
__device__ float g_wr  [40370176];

__constant__ int c_dils[NHEADS][3] = {
    {1,2,4},{1,1,1},{4,8,16},{8,16,32},{32,64,128},{64,128,256},
    {256,512,1024},{1,100,200},{1,500,1000},{1,1024,2048},{3,9,27},{5,25,125}};

__device__ __forceinline__ float sigf(float v){ return 1.f/(1.f+expf(-v)); }
__device__ __forceinline__ float geluf(float v){ return 0.5f*v*(1.f+erff(v*0.70710678118654752f)); }
__device__ __forceinline__ float rtf(float v){
    float r; asm("cvt.rna.tf32.f32 %0, %1;" : "=f"(r) : "f"(v)); return r;
}
__device__ __forceinline__ uint32_t s2u(const void* p){
    uint32_t a;
    asm("{ .reg .u64 t; cvta.to.shared.u64 t, %1; cvt.u32.u64 %0, t; }" : "=r"(a) : "l"(p));
    return a;
}
__device__ __forceinline__ void cpa16(void* dst, const void* src){
    uint32_t d = s2u(dst);
    asm volatile("cp.async.cg.shared.global [%0], [%1], 16;" :: "r"(d), "l"(src) : "memory");
}
#define CPA_COMMIT() asm volatile("cp.async.commit_group;" ::: "memory")
#define CPA_WAIT2()  asm volatile("cp.async.wait_group 2;" ::: "memory")

__device__ __forceinline__ void mma8(float* c, const uint32_t* a, const uint32_t* b){
    asm volatile("mma.sync.aligned.m16n8k8.row.col.f32.tf32.tf32.f32 "
        "{%0,%1,%2,%3}, {%4,%5,%6,%7}, {%8,%9}, {%0,%1,%2,%3};"
        : "+f"(c[0]), "+f"(c[1]), "+f"(c[2]), "+f"(c[3])
        : "r"(a[0]), "r"(a[1]), "r"(a[2]), "r"(a[3]),
          "r"(b[0]), "r"(b[1]));
}

// ============================================================ big tf32 GEMM
// C[M,N] = A[M,K] @ W[N,K]^T ; 128x256 CTA tile, 64x64 warp tile, cp.async x3
// smem per stage: A[128][20] + B[256][20] floats (7680 floats)
#define GSTRIDE 20
#define GSTAGEF 7680
__global__ void __launch_bounds__(256)
mma_gemm_big(const float* __restrict__ A, long lda,
             const float* __restrict__ W, long ldw,
             float* __restrict__ C, long ldc,
             int K, int epi, int rnd,
             const float* __restrict__ bias,
             const float* __restrict__ resid,
             const float* __restrict__ gate)
{
    extern __shared__ float gs[];
    int tid = threadIdx.x, lane = tid & 31, warp = tid >> 5;
    int wm = warp & 1, wn = warp >> 1;         // 2 x 4 warps
    int r = lane >> 2, cl = lane & 3;
    long bm = (long)blockIdx.y*128, bn = (long)blockIdx.x*256;

    float acc[4][8][4];
    #pragma unroll
    for (int i=0;i<4;i++)
        #pragma unroll
        for (int j=0;j<8;j++)
            #pragma unroll
            for (int q=0;q<4;q++) acc[i][j][q]=0.f;

    // per-thread fixed chunk mapping (6 chunks of 16B per stage)
    const float* srcA[2]; float* dstA[2];
    const float* srcB[4]; float* dstB[4];
    {
        #pragma unroll
        for (int p=0;p<2;p++){
            int q = tid + p*256;          // q < 512 : A chunks
            int m = q >> 2, kc = q & 3;
            srcA[p] = A + (bm + m)*lda + kc*4;
            dstA[p] = gs + m*GSTRIDE + kc*4;
        }
        #pragma unroll
        for (int p=0;p<4;p++){
            int qb = tid + p*256;         // B chunks 0..1023
            int n = qb >> 2, kc = qb & 3;
            srcB[p] = W + (bn + n)*ldw + kc*4;
            dstB[p] = gs + 128*GSTRIDE + n*GSTRIDE + kc*4;
        }
    }
    const int iters = K >> 4;

    // prologue: stages 0,1
    #pragma unroll
    for (int s=0;s<2;s++){
        long k0 = (long)s*16;
        #pragma unroll
        for (int p=0;p<2;p++) cpa16(dstA[p] + s*GSTAGEF, srcA[p] + k0);
        #pragma unroll
        for (int p=0;p<4;p++) cpa16(dstB[p] + s*GSTAGEF, srcB[p] + k0);
        CPA_COMMIT();
    }

    for (int i = 0; i < iters; i++){
        int nstage = i + 2;
        if (nstage < iters){
            int sb = nstage - (nstage/3)*3;
            long k0 = (long)nstage*16;
            #pragma unroll
            for (int p=0;p<2;p++) cpa16(dstA[p] + sb*GSTAGEF, srcA[p] + k0);
            #pragma unroll
            for (int p=0;p<4;p++) cpa16(dstB[p] + sb*GSTAGEF, srcB[p] + k0);
        }
        CPA_COMMIT();
        CPA_WAIT2();
        __syncthreads();
        int cs = i - (i/3)*3;
        const float* Asm = gs + cs*GSTAGEF;
        const float* Bsm = Asm + 128*GSTRIDE;
        #pragma unroll
        for (int kk = 0; kk < 2; kk++){
            int kb = kk*8;
            uint32_t af[4][4], bf[8][2];
            #pragma unroll
            for (int mt=0;mt<4;mt++){
                int m0 = wm*64 + mt*16;
                af[mt][0] = __float_as_uint(Asm[(m0+r  )*GSTRIDE + kb+cl  ]);
                af[mt][1] = __float_as_uint(Asm[(m0+r+8)*GSTRIDE + kb+cl  ]);
                af[mt][2] = __float_as_uint(Asm[(m0+r  )*GSTRIDE + kb+cl+4]);
                af[mt][3] = __float_as_uint(Asm[(m0+r+8)*GSTRIDE + kb+cl+4]);
            }
            #pragma unroll
            for (int nt=0;nt<8;nt++){
                int n0 = wn*64 + nt*8;
                bf[nt][0] = __float_as_uint(Bsm[(n0+r)*GSTRIDE + kb+cl  ]);
                bf[nt][1] = __float_as_uint(Bsm[(n0+r)*GSTRIDE + kb+cl+4]);
            }
            #pragma unroll
            for (int mt=0;mt<4;mt++)
                #pragma unroll
                for (int nt=0;nt<8;nt++)
                    mma8(acc[mt][nt], af[mt], bf[nt]);
        }
        __syncthreads();
    }

    // epilogue
    #pragma unroll
    for (int mt=0;mt<4;mt++){
        #pragma unroll
        for (int nt=0;nt<8;nt++){
            long row0 = bm + wm*64 + mt*16 + r;
            long col  = bn + wn*64 + nt*8 + 2*cl;
            #pragma unroll
            for (int hh=0;hh<2;hh++){
                long row = row0 + hh*8;
                float v0 = acc[mt][nt][hh*2+0];
                float v1 = acc[mt][nt][hh*2+1];
                if (bias){ v0 += bias[col]; v1 += bias[col+1]; }
                if (epi == 1){
                    float g = gate[row];
                    v0 = resid[row*ldc + col]   + g*v0;
                    v1 = resid[row*ldc + col+1] + g*v1;
                } else if (epi == 2){
                    v0 = A[row*lda + col]   * sigf(v0);
                    v1 = A[row*lda + col+1] * sigf(v1);
                }
                if (rnd){ v0 = rtf(v0); v1 = rtf(v1); }
                float2 o; o.x = v0; o.y = v1;
                *(float2*)(C + row*ldc + col) = o;
            }
        }
    }
}

// ============================================================ small GEMM (mem heads) — proven R4 kernel
__global__ void __launch_bounds__(256)
mma_gemm_small(const float* __restrict__ A, long lda, long aZ,
               const float* __restrict__ W, long ldw, long wZ,
               float* __restrict__ C, long ldc, long cZ, int K)
{
    __shared__ float As[2][16][136];
    __shared__ float Bs[2][16][136];
    int tid = threadIdx.x, lane = tid & 31, warp = tid >> 5;
    int wm = warp & 1, wn = warp >> 1;
    int r = lane >> 2, cl = lane & 3;
    long bm = (long)blockIdx.y*128, bn = (long)blockIdx.x*128;
    A += (long)blockIdx.z*aZ;
    W += (long)blockIdx.z*wZ;
    C += (long)blockIdx.z*cZ;

    float acc[4][4][4];
    #pragma unroll
    for (int i=0;i<4;i++)
        #pragma unroll
        for (int j=0;j<4;j++)
            #pragma unroll
            for (int q=0;q<4;q++) acc[i][j][q]=0.f;

    int lm = tid & 127;
    int kq = tid >> 7;
    const float* Ab = A + (bm + lm)*lda + kq*4;
    const float* Wb = W + (bn + lm)*ldw + kq*4;
    const int iters = K >> 4;
    {
        float4 a0 = *(const float4*)(Ab);
        float4 a1 = *(const float4*)(Ab + 8);
        float4 b0 = *(const float4*)(Wb);
        float4 b1 = *(const float4*)(Wb + 8);
        #pragma unroll
        for (int j=0;j<4;j++){
            As[0][kq*4+j][lm]   = ((const float*)&a0)[j];
            As[0][kq*4+8+j][lm] = ((const float*)&a1)[j];
            Bs[0][kq*4+j][lm]   = ((const float*)&b0)[j];
            Bs[0][kq*4+8+j][lm] = ((const float*)&b1)[j];
        }
    }
    __syncthreads();
    for (int i = 0; i < iters; i++){
        int bsel = i & 1;
        float4 a0, a1, b0, b1;
        if (i+1 < iters){
            const float* Ap = Ab + (long)(i+1)*16;
            const float* Wp = Wb + (long)(i+1)*16;
            a0 = *(const float4*)(Ap);  a1 = *(const float4*)(Ap + 8);
            b0 = *(const float4*)(Wp);  b1 = *(const float4*)(Wp + 8);
        }
        #pragma unroll
        for (int kk = 0; kk < 2; kk++){
            int kb = kk*8;
            uint32_t af[4][4], bf[4][2];
            #pragma unroll
            for (int mt=0;mt<4;mt++){
                int m0 = wm*64 + mt*16;
                af[mt][0] = __float_as_uint(As[bsel][kb+cl  ][m0+r  ]);
                af[mt][1] = __float_as_uint(As[bsel][kb+cl  ][m0+r+8]);
                af[mt][2] = __float_as_uint(As[bsel][kb+cl+4][m0+r  ]);
                af[mt][3] = __float_as_uint(As[bsel][kb+cl+4][m0+r+8]);
            }
            #pragma unroll
            for (int nt=0;nt<4;nt++){
                int n0 = wn*32 + nt*8;
                bf[nt][0] = __float_as_uint(Bs[bsel][kb+cl  ][n0+r]);
                bf[nt][1] = __float_as_uint(Bs[bsel][kb+cl+4][n0+r]);
            }
            #pragma unroll
            for (int mt=0;mt<4;mt++)
                #pragma unroll
                for (int nt=0;nt<4;nt++)
                    mma8(acc[mt][nt], af[mt], bf[nt]);
        }
        if (i+1 < iters){
            __syncthreads();
            int nb = (i+1)&1;
            #pragma unroll
            for (int j=0;j<4;j++){
                As[nb][kq*4+j][lm]   = ((const float*)&a0)[j];
                As[nb][kq*4+8+j][lm] = ((const float*)&a1)[j];
                Bs[nb][kq*4+j][lm]   = ((const float*)&b0)[j];
                Bs[nb][kq*4+8+j][lm] = ((const float*)&b1)[j];
            }
            __syncthreads();
        }
    }
    #pragma unroll
    for (int mt=0;mt<4;mt++){
        #pragma unroll
        for (int nt=0;nt<4;nt++){
            long row0 = bm + wm*64 + mt*16 + r;
            long col  = bn + wn*32 + nt*8 + 2*cl;
            #pragma unroll
            for (int hh=0;hh<2;hh++){
                long row = row0 + hh*8;
                float2 o; o.x = acc[mt][nt][hh*2+0]; o.y = acc[mt][nt][hh*2+1];
                *(float2*)(C + row*ldc + col) = o;
            }
        }
    }
}

// ------------------------------------------------------------ weight rounding
__global__ void __launch_bounds__(256) roundw_kernel(
    const float4* __restrict__ in, float4* __restrict__ out, int n4)
{
    int i = blockIdx.x*256 + threadIdx.x;
    if (i < n4){
        float4 v = in[i];
        v.x = rtf(v.x); v.y = rtf(v.y); v.z = rtf(v.z); v.w = rtf(v.w);
        out[i] = v;
    }
}

// ------------------------------------------------------------ rms + gate (+router)
__global__ void __launch_bounds__(256) rms_router_kernel(
    const float* __restrict__ x, const float* __restrict__ nw,
    const float* __restrict__ gw, const float* __restrict__ gb,
    float* __restrict__ y, float* __restrict__ gate,
    const float* __restrict__ rw, const float* __restrict__ rb,
    float* __restrict__ hw, int doRound)
{
    __shared__ float sy[HDIM];
    __shared__ float red[256];
    int t = blockIdx.x, tid = threadIdx.x;
    const float* xr = x + (size_t)t*HDIM;
    float ss = 0.f, gd = 0.f;
    for (int i = tid; i < HDIM; i += 256){
        float v = xr[i]; sy[i] = v; ss += v*v; gd += v*gw[i];
    }
    red[tid] = ss; __syncthreads();
    for (int s = 128; s > 0; s >>= 1){ if (tid < s) red[tid] += red[tid+s]; __syncthreads(); }
    float rs = rsqrtf(red[0]*(1.f/HDIM) + 1e-6f);
    __syncthreads();
    red[tid] = gd; __syncthreads();
    for (int s = 128; s > 0; s >>= 1){ if (tid < s) red[tid] += red[tid+s]; __syncthreads(); }
    if (tid == 0) gate[t] = sigf(red[0] + gb[0]);
    float* yr = y + (size_t)t*HDIM;
    for (int i = tid; i < HDIM; i += 256){
        float v = sy[i]*rs*nw[i];
        yr[i] = doRound ? rtf(v) : v;
        sy[i] = v;
    }
    if (rw){
        __syncthreads();
        int warp = tid >> 5, lane = tid & 31;
        for (int r = warp; r < NHEADS; r += 8){
            float s = 0.f;
            for (int i = lane; i < HDIM; i += 32) s += sy[i]*rw[r*HDIM + i];
            #pragma unroll
            for (int o = 16; o; o >>= 1) s += __shfl_down_sync(0xffffffffu, s, o);
            if (lane == 0) hw[(size_t)t*NHEADS + r] = sigf(s + rb[r]);
        }
    }
}

// ------------------------------------------------------------ fused 6-stage conv stack
// block = (batch, 8-channel group); full sequence in smem ping-pong
__global__ void __launch_bounds__(256) convfused_kernel(
    const float* __restrict__ in, float* __restrict__ out,
    const float* __restrict__ w, const float* __restrict__ b)
{
    extern __shared__ float cs[];
    float* buf0 = cs;
    float* buf1 = cs + SL*8;
    int cg = blockIdx.x % (HDIM/8);
    int bb = blockIdx.x / (HDIM/8);
    int c0 = cg*8;
    int tid = threadIdx.x;
    const float* base = in + (size_t)bb*SL*HDIM + c0;
    for (int e = tid; e < SL*8; e += 256){
        int t = e >> 3, c = e & 7;
        buf0[e] = base[(size_t)t*HDIM + c];
    }
    __syncthreads();
    float* src = buf0; float* dst = buf1;
    int c = tid & 7;
    #pragma unroll
    for (int j = 0; j < 6; j++){
        int dil = 1 << j;
        float w0 = w[(j*HDIM + c0 + c)*KW + 0];
        float w1 = w[(j*HDIM + c0 + c)*KW + 1];
        float w2 = w[(j*HDIM + c0 + c)*KW + 2];
        float w3 = w[(j*HDIM + c0 + c)*KW + 3];
        float bj = b[j*HDIM + c0 + c];
        for (int t = tid >> 3; t < SL; t += 32){
            float xv = src[t*8 + c];
            float a = bj + xv*w3;
            int t1 = t - dil, t2 = t - 2*dil, t3 = t - 3*dil;
            if (t1 >= 0) a += src[t1*8 + c]*w2;
            if (t2 >= 0) a += src[t2*8 + c]*w1;
            if (t3 >= 0) a += src[t3*8 + c]*w0;
            dst[t*8 + c] = xv + geluf(a);
        }
        __syncthreads();
        float* tmp = src; src = dst; dst = tmp;
    }
    float* obase = out + (size_t)bb*SL*HDIM + c0;
    for (int e = tid; e < SL*8; e += 256){
        int t = e >> 3, cc = e & 7;
        obase[(size_t)t*HDIM + cc] = rtf(src[e]);
    }
}

// ------------------------------------------------------------ per-head conv (float4)
__global__ void __launch_bounds__(256) headconv_v4(
    const float4* __restrict__ in, float4* __restrict__ out,
    const float* __restrict__ w, const float* __restrict__ b, int stage)
{
    const int C4 = HDIM/4;
    int idx = blockIdx.x*256 + threadIdx.x;
    int c4 = idx % C4;
    int tok = idx / C4;
    int t = tok & (SL-1);
    int head = c4 >> 5;
    int d = (c4 & 31)*4;
    int dil = c_dils[head][stage];
    int wb = (head*3 + stage)*HDH + d;
    float4 acc = *(const float4*)(b + wb);
    float4 xv = in[idx];
    #pragma unroll
    for (int k = 0; k < KW-1; k++){
        int tt = t - (KW-1-k)*dil;
        if (tt >= 0){
            float4 iv = in[idx + (tt - t)*C4];
            acc.x += iv.x * w[(wb+0)*KW + k];
            acc.y += iv.y * w[(wb+1)*KW + k];
            acc.z += iv.z * w[(wb+2)*KW + k];
            acc.w += iv.w * w[(wb+3)*KW + k];
        }
    }
    acc.x += xv.x * w[(wb+0)*KW + 3];
    acc.y += xv.y * w[(wb+1)*KW + 3];
    acc.z += xv.z * w[(wb+2)*KW + 3];
    acc.w += xv.w * w[(wb+3)*KW + 3];
    float4 o; o.x = xv.x + acc.x; o.y = xv.y + acc.y; o.z = xv.z + acc.z; o.w = xv.w + acc.w;
    out[idx] = o;
}

// ------------------------------------------------------------ combine heads (float4)
__global__ void __launch_bounds__(256) combine_v4(
    const float4* __restrict__ hbuf, const float4* __restrict__ memout,
    const float* __restrict__ hw, float4* __restrict__ out)
{
    const int C4 = HDIM/4;
    int idx = blockIdx.x*256 + threadIdx.x;
    int c4 = idx % C4;
    long tok = idx / C4;
    int head = c4 >> 5;
    float4 v = hbuf[idx];
    if (head >= 6 && head <= 9){
        float4 mv = memout[tok*128 + (head-6)*32 + (c4 & 31)];
        v.x += mv.x; v.y += mv.y; v.z += mv.z; v.w += mv.w;
    }
    float g = hw[tok*NHEADS + head];
    float4 o;
    o.x = rtf(v.x*g); o.y = rtf(v.y*g); o.z = rtf(v.z*g); o.w = rtf(v.w*g);
    out[idx] = o;
}

// ------------------------------------------------------------ GLU (float4)
__global__ void __launch_bounds__(256) glu_v4(
    const float4* __restrict__ big, float4* __restrict__ out, int N4)
{
    long idx = (long)blockIdx.x*256 + threadIdx.x;
    if (idx >= (long)NT*N4) return;
    long m = idx / N4; int n = (int)(idx % N4);
    float4 c = big[m*2*N4 + n];
    float4 g = big[m*2*N4 + N4 + n];
    float4 o;
    o.x = rtf(c.x*sigf(g.x)); o.y = rtf(c.y*sigf(g.y));
    o.z = rtf(c.z*sigf(g.z)); o.w = rtf(c.w*sigf(g.w));
    out[idx] = o;
}

// ------------------------------------------------------------ memory write-gate
__global__ void __launch_bounds__(128) memgate_kernel(
    const float* __restrict__ xh, const float* __restrict__ wg,
    const float* __restrict__ bg, float* __restrict__ g)
{
    __shared__ float red[128];
    int t = blockIdx.x, tid = threadIdx.x;
    for (int h = 0; h < 4; h++){
        float v = xh[(size_t)t*HDIM + (6+h)*HDH + tid] * wg[h*HDH + tid];
        red[tid] = v; __syncthreads();
        for (int s = 64; s > 0; s >>= 1){ if (tid < s) red[tid] += red[tid+s]; __syncthreads(); }
        if (tid == 0) g[t*4 + h] = sigf(red[0] + bg[h]);
        __syncthreads();
    }
}

// ------------------------------------------------------------ memory scan
#define SCAN_SMEM ((64*QS*2 + 64*MT + 64 + 128*(MT+1) + 4)*4)
__global__ void __launch_bounds__(256) memscan_kernel(
    const float* __restrict__ q, const float* __restrict__ k,
    const float* __restrict__ v, const float* __restrict__ g,
    float* __restrict__ reads)
{
    extern __shared__ float smem[];
    float* sQ  = smem;
    float* sK  = sQ + 64*QS;
    float* sV  = sK + 64*QS;
    float* sG  = sV + 64*MT;
    float* sM  = sG + 64;
    float* sDec= sM + 128*(MT+1);
    int tid  = threadIdx.x;
    int mblk = blockIdx.x & 15;
    int h    = (blockIdx.x >> 4) & 3;
    int b    = blockIdx.x >> 6;
    int m0   = mblk * MT;
    for (int i = tid; i < 128*(MT+1); i += 256) sM[i] = 0.f;
    for (int c = 0; c < NCHUNK; c++){
        int tok0 = b*SL + c*CHUNK;
        __syncthreads();
        if (tid < 64) sG[tid] = g[(tok0 + tid)*4 + h];
        __syncthreads();
        #pragma unroll
        for (int it = 0; it < 8; it++){
            int li = tid + it*256;
            int s  = li >> 5;
            int e4 = (li & 31) << 2;
            size_t gi = ((size_t)(tok0 + s)*4 + h)*HDH + e4;
            float4 qa = *(const float4*)(q + gi);
            float4 ka = *(const float4*)(k + gi);
            float gs = sG[s];
            int so = s*QS + e4;
            sQ[so] = qa.x; sQ[so+1] = qa.y; sQ[so+2] = qa.z; sQ[so+3] = qa.w;
            sK[so] = ka.x*gs; sK[so+1] = ka.y*gs; sK[so+2] = ka.z*gs; sK[so+3] = ka.w*gs;
        }
        if (tid < 128){
            int s = tid >> 1; int mm = (tid & 1)*4;
            float4 va = *(const float4*)(v + ((size_t)(tok0 + s)*4 + h)*HDH + m0 + mm);
            float* dv = &sV[s*MT + mm];
            dv[0]=va.x; dv[1]=va.y; dv[2]=va.z; dv[3]=va.w;
        }
        __syncthreads();
        if (tid < 32){
            float dsum = sG[tid] + sG[tid + 32];
            #pragma unroll
            for (int o = 16; o; o >>= 1) dsum += __shfl_down_sync(0xffffffffu, dsum, o);
            if (tid == 0) sDec[0] = 1.f - dsum*(1.f/64.f);
        }
        {
            int s  = tid & 63;
            int mi = (tid >> 6)*2;
            float a0 = 0.f, a1 = 0.f;
            const float* qr = sQ + s*QS;
            #pragma unroll 8
            for (int d = 0; d < HDH; d++){
                float qv = qr[d];
                a0 += qv * sM[d*(MT+1) + mi];
                a1 += qv * sM[d*(MT+1) + mi + 1];
            }
            size_t ro = ((size_t)(tok0 + s)*4 + h)*HDH + m0 + mi;
            reads[ro] = rtf(a0); reads[ro+1] = rtf(a1);
        }
        __syncthreads();
        {
            int d  = tid & 127;
            int mb = (tid >> 7)*4;
            float dec = sDec[0];
            float a0 = dec*sM[d*(MT+1)+mb+0];
            float a1 = dec*sM[d*(MT+1)+mb+1];
            float a2 = dec*sM[d*(MT+1)+mb+2];
            float a3 = dec*sM[d*(MT+1)+mb+3];
            #pragma unroll 8
            for (int s = 0; s < 64; s++){
                float kgv = sK[s*QS + d];
                const float* vr = sV + s*MT + mb;
                a0 += kgv*vr[0]; a1 += kgv*vr[1]; a2 += kgv*vr[2]; a3 += kgv*vr[3];
            }
            sM[d*(MT+1)+mb+0]=a0; sM[d*(MT+1)+mb+1]=a1;
            sM[d*(MT+1)+mb+2]=a2; sM[d*(MT+1)+mb+3]=a3;
        }
    }
}

// ------------------------------------------------------------ host side
static float* F(const void* sym){
    void* p = nullptr;
    cudaGetSymbolAddress(&p, sym);
    return (float*)p;
}

#define GEMM_SMEM (3*GSTAGEF*4)
#define CONV_SMEM (2*SL*8*4)

static void gemmBig(const float* A, const float* W, float* C,
                    long lda, long ldw, long ldc, int M, int N, int K,
                    int epi, int rnd, const float* bias,
                    const float* resid, const float* gate)
{
    dim3 g(N/256, M/128, 1);
    mma_gemm_big<<<g, 256, GEMM_SMEM>>>(A, lda, W, ldw, C, ldc,
                                        K, epi, rnd, bias, resid, gate);
}
static void gemmMem(const float* A, long lda, long aZ,
                    const float* W, float* C, long cZ)
{
    dim3 g(1, NT/128, 4);
    mma_gemm_small<<<g, 256>>>(A, lda, aZ, W, 128, 16384, C, 512, cZ, 128);
}
static void roundw(const float* in, float* out, size_t n){
    int n4 = (int)(n/4);
    roundw_kernel<<<(n4 + 255)/256, 256>>>((const float4*)in, (float4*)out, n4);
}

extern "C" void kernel_launch(void* const* d_in, const int* in_sizes, int n_in,
                              void* d_out, int out_size)
{
    const float* x            = (const float*)d_in[0];
    const float* norm1_w      = (const float*)d_in[1];
    const float* norm2_w      = (const float*)d_in[2];
    const float* norm3_w      = (const float*)d_in[3];
    const float* convstack_w  = (const float*)d_in[4];
    const float* convstack_b  = (const float*)d_in[5];
    const float* conv_proj_w  = (const float*)d_in[6];
    const float* conv_proj_b  = (const float*)d_in[7];
    const float* gate_proj_w  = (const float*)d_in[8];
    const float* head_router_w= (const float*)d_in[9];
    const float* head_router_b= (const float*)d_in[10];
    const float* head_conv_w  = (const float*)d_in[11];
    const float* head_conv_b  = (const float*)d_in[12];
    const float* mem_Wq       = (const float*)d_in[13];
    const float* mem_Wk       = (const float*)d_in[14];
    const float* mem_Wv       = (const float*)d_in[15];
    const float* mem_Wg_w     = (const float*)d_in[16];
    const float* mem_Wg_b     = (const float*)d_in[17];
    const float* mem_Wout     = (const float*)d_in[18];
    const float* mix_gate_w   = (const float*)d_in[19];
    const float* mix_gate_b   = (const float*)d_in[20];
    const float* mixing_w     = (const float*)d_in[21];
    const float* mixing_b     = (const float*)d_in[22];
    const float* ffn_in_w     = (const float*)d_in[23];
    const float* ffn_out_w    = (const float*)d_in[24];
    const float* conv_gate_w  = (const float*)d_in[25];
    const float* conv_gate_b  = (const float*)d_in[26];
    const float* state_gate_w = (const float*)d_in[27];
    const float* state_gate_b = (const float*)d_in[28];
    const float* ffn_gate_w   = (const float*)d_in[29];
    const float* ffn_gate_b   = (const float*)d_in[30];
    float* out = (float*)d_out;

    float* y    = F(g_y);
    float* t0   = F(g_t0);
    float* t1   = F(g_t1);
    float* xh   = F(g_xh);
    float* h2   = F(g_h2);
    float* big  = F(g_big);
    float* ffn  = F(g_ffn);
    float* qb   = F(g_q);
    float* kb   = F(g_k);
    float* vb   = F(g_v);
    float* rd   = F(g_rd);
    float* mo   = F(g_mo);
    float* gm   = F(g_gm);
    float* hw   = F(g_hw);
    float* gate = F(g_gate);
    float* wr   = F(g_wr);

    float* w_cp  = wr;                 // conv_proj   2359296
    float* w_gp  = wr + 2359296;       // gate_proj   4718592
    float* w_q   = wr + 7077888;
    float* w_k   = wr + 7143424;
    float* w_v   = wr + 7208960;
    float* w_o   = wr + 7274496;
    float* w_mg  = wr + 7340032;       // mix_gate
    float* w_mx  = wr + 9699328;       // mixing
    float* w_fi  = wr + 12058624;      // ffn_in
    float* w_fo  = wr + 30932992;      // ffn_out

    cudaFuncSetAttribute(memscan_kernel,
        cudaFuncAttributeMaxDynamicSharedMemorySize, SCAN_SMEM);
    cudaFuncSetAttribute(mma_gemm_big,
        cudaFuncAttributeMaxDynamicSharedMemorySize, GEMM_SMEM);
    cudaFuncSetAttribute(convfused_kernel,
        cudaFuncAttributeMaxDynamicSharedMemorySize, CONV_SMEM);

    const int EW4 = NT*HDIM/4/256;

    // launches 1-3: rounding needed early (keeps launch #6 = big GEMM for ncu)
    roundw(conv_proj_w, w_cp, 2359296);      // 1
    roundw(gate_proj_w, w_gp, 4718592);      // 2
    roundw(mix_gate_w,  w_mg, 2359296);      // 3

    // ============ stage A: conv branch ============
    rms_router_kernel<<<NT,256>>>(x, norm1_w, conv_gate_w, conv_gate_b,
                                  y, gate, nullptr, nullptr, nullptr, 0);   // 4
    convfused_kernel<<<BB*(HDIM/8), 256, CONV_SMEM>>>(y, t0,
                                  convstack_w, convstack_b);                // 5
    gemmBig(t0, w_cp, out, HDIM, HDIM, HDIM, NT, HDIM, HDIM, 1, 0,
            conv_proj_b, x, gate);                                          // 6 <- ncu

    // remaining weight rounding
    roundw(mixing_w, w_mx, 2359296);
    roundw(ffn_in_w, w_fi, 18874368);
    roundw(ffn_out_w, w_fo, 9437184);
    roundw(mem_Wq, w_q, 65536);
    roundw(mem_Wk, w_k, 65536);
    roundw(mem_Wv, w_v, 65536);
    roundw(mem_Wout, w_o, 65536);

    // ============ stage B: state branch ============
    rms_router_kernel<<<NT,256>>>(out, norm2_w, state_gate_w, state_gate_b,
                                  y, gate, head_router_w, head_router_b, hw, 1);
    gemmBig(y, w_gp, big, HDIM, HDIM, 2*HDIM, NT, 2*HDIM, HDIM, 0, 0,
            nullptr, nullptr, nullptr);
    glu_v4<<<EW4,256>>>((const float4*)big, (float4*)xh, HDIM/4);
    memgate_kernel<<<NT,128>>>(xh, mem_Wg_w, mem_Wg_b, gm);
    gemmMem(xh + 6*HDH, HDIM, HDH, w_q, qb, HDH);
    gemmMem(xh + 6*HDH, HDIM, HDH, w_k, kb, HDH);
    gemmMem(xh + 6*HDH, HDIM, HDH, w_v, vb, HDH);
    memscan_kernel<<<BB*4*(MEMD/MT), 256, SCAN_SMEM>>>(qb, kb, vb, gm, rd);
    gemmMem(rd, 512, HDH, w_o, mo, HDH);
    headconv_v4<<<EW4,256>>>((const float4*)xh, (float4*)h2, head_conv_w, head_conv_b, 0);
    headconv_v4<<<EW4,256>>>((const float4*)h2, (float4*)xh, head_conv_w, head_conv_b, 1);
    headconv_v4<<<EW4,256>>>((const float4*)xh, (float4*)h2, head_conv_w, head_conv_b, 2);
    combine_v4<<<EW4,256>>>((const float4*)h2, (const float4*)mo, hw, (float4*)t0);
    gemmBig(t0, w_mg, t1, HDIM, HDIM, HDIM, NT, HDIM, HDIM, 2, 1,
            mix_gate_b, nullptr, nullptr);
    gemmBig(t1, w_mx, out, HDIM, HDIM, HDIM, NT, HDIM, HDIM, 1, 0,
            mixing_b, out, gate);

    // ============ stage C: FFN ============
    rms_router_kernel<<<NT,256>>>(out, norm3_w, ffn_gate_w, ffn_gate_b,
                                  y, gate, nullptr, nullptr, nullptr, 1);
    gemmBig(y, w_fi, big, HDIM, HDIM, 2*INNERD, NT, 2*INNERD, HDIM, 0, 0,
            nullptr, nullptr, nullptr);
    glu_v4<<<(NT*INNERD/4 + 255)/256, 256>>>((const float4*)big, (float4*)ffn, INNERD/4);
    gemmBig(ffn, w_fo, out, INNERD, INNERD, HDIM, NT, HDIM, INNERD, 1, 0,
            nullptr, out, gate);
}

// round 6
// speedup vs baseline: 4.8881x; 1.6485x over previous
#include <cuda_runtime.h>
#include <cuda_fp16.h>
#include <math.h>
#include <stdint.h>

#define HDIM   1536
#define BB     4
#define SL     2048
#define NHEADS 12
#define HDH    128
#define MEMD   128
#define INNERD 6144
#define NT     (BB*SL)
#define KW     4
#define CHUNK  64
#define NCHUNK (SL/CHUNK)
#define MT     8
#define QS     129

// ------------------------------------------------------------------ scratch
__device__ float g_y   [(size_t)NT*HDIM];
__device__ float g_h2a [(size_t)NT*HDIM];
__device__ float g_xh  [(size_t)NT*HDIM];
__device__ float g_h2  [(size_t)NT*HDIM];
__device__ float g_big [(size_t)NT*2*INNERD];
__device__ float g_q   [(size_t)NT*4*HDH];
__device__ float g_k   [(size_t)NT*4*HDH];
__device__ float g_v   [(size_t)NT*4*HDH];
__device__ float g_rd  [(size_t)NT*4*HDH];
__device__ float g_mo  [(size_t)NT*4*HDH];
__device__ float g_gm  [(size_t)NT*4];
__device__ float g_hw  [(size_t)NT*NHEADS];
__device__ float g_gate[NT];
__device__ float g_wr  [4*65536];                 // tf32 mem weights
__device__ __half g_hy  [(size_t)NT*HDIM];        // rms out (fp16)
__device__ __half g_ht0 [(size_t)NT*HDIM];        // convfused out
__device__ __half g_htc [(size_t)NT*HDIM];        // combine out
__device__ __half g_ht1 [(size_t)NT*HDIM];        // mix_gate out
__device__ __half g_hffn[(size_t)NT*INNERD];      // glu ffn out
__device__ __half g_hwt [40108032];               // fp16 weights

__constant__ int c_dils[NHEADS][3] = {
    {1,2,4},{1,1,1},{4,8,16},{8,16,32},{32,64,128},{64,128,256},
    {256,512,1024},{1,100,200},{1,500,1000},{1,1024,2048},{3,9,27},{5,25,125}};

__device__ __forceinline__ float sigf(float v){ return 1.f/(1.f+expf(-v)); }
__device__ __forceinline__ float geluf(float v){ return 0.5f*v*(1.f+erff(v*0.70710678118654752f)); }
__device__ __forceinline__ float rtf(float v){
    float r; asm("cvt.rna.tf32.f32 %0, %1;" : "=f"(r) : "f"(v)); return r;
}
__device__ __forceinline__ uint32_t s2u(const void* p){
    uint32_t a;
    asm("{ .reg .u64 t; cvta.to.shared.u64 t, %1; cvt.u32.u64 %0, t; }" : "=r"(a) : "l"(p));
    return a;
}
__device__ __forceinline__ void cpa16(void* dst, const void* src){
    uint32_t d = s2u(dst);
    asm volatile("cp.async.cg.shared.global [%0], [%1], 16;" :: "r"(d), "l"(src) : "memory");
}
#define CPA_COMMIT() asm volatile("cp.async.commit_group;" ::: "memory")
#define CPA_WAIT2()  asm volatile("cp.async.wait_group 2;" ::: "memory")

__device__ __forceinline__ void mma8(float* c, const uint32_t* a, const uint32_t* b){
    asm volatile("mma.sync.aligned.m16n8k8.row.col.f32.tf32.tf32.f32 "
        "{%0,%1,%2,%3}, {%4,%5,%6,%7}, {%8,%9}, {%0,%1,%2,%3};"
        : "+f"(c[0]), "+f"(c[1]), "+f"(c[2]), "+f"(c[3])
        : "r"(a[0]), "r"(a[1]), "r"(a[2]), "r"(a[3]),
          "r"(b[0]), "r"(b[1]));
}
__device__ __forceinline__ void mma16h(float* c, const uint32_t* a, const uint32_t* b){
    asm volatile("mma.sync.aligned.m16n8k16.row.col.f32.f16.f16.f32 "
        "{%0,%1,%2,%3}, {%4,%5,%6,%7}, {%8,%9}, {%0,%1,%2,%3};"
        : "+f"(c[0]), "+f"(c[1]), "+f"(c[2]), "+f"(c[3])
        : "r"(a[0]), "r"(a[1]), "r"(a[2]), "r"(a[3]),
          "r"(b[0]), "r"(b[1]));
}

// ============================================================ fp16 big GEMM
// C[M,N] = A[M,K] @ W[N,K]^T, half operands, fp32 accum.
// CTA 128x256, warp 64x64 (2x4 warps), BK=32, 3-stage cp.async.
// smem row = 32 halves + 8 pad = 20 words; stage = (128+256)*20 = 7680 words
#define HSTRIDE 20
#define HSTAGE  7680
// epi 0: acc(+bias) -> fp32 or fp16 (outH)
// epi 1: resid + gate[row]*(acc+bias) -> fp32
// epi 2: A[row,col]*sigmoid(acc+bias) -> fp16
__global__ void __launch_bounds__(256)
mma_gemm_h(const __half* __restrict__ A, long lda,
           const __half* __restrict__ W, long ldw,
           void* __restrict__ Cv, long ldc,
           int K, int epi, int outH,
           const float* __restrict__ bias,
           const float* __restrict__ resid,
           const float* __restrict__ gate)
{
    extern __shared__ float gs[];
    uint32_t* su = (uint32_t*)gs;
    int tid = threadIdx.x, lane = tid & 31, warp = tid >> 5;
    int wm = warp & 1, wn = warp >> 1;
    int r = lane >> 2, cl = lane & 3;
    long bm = (long)blockIdx.y*128, bn = (long)blockIdx.x*256;

    float acc[4][8][4];
    #pragma unroll
    for (int i=0;i<4;i++)
        #pragma unroll
        for (int j=0;j<8;j++)
            #pragma unroll
            for (int q=0;q<4;q++) acc[i][j][q]=0.f;

    // chunk mapping: 1536 x 16B chunks per stage, 6 per thread
    const __half* srcA[2]; float* dstA[2];
    const __half* srcB[4]; float* dstB[4];
    #pragma unroll
    for (int p=0;p<2;p++){
        int q = tid + p*256;             // A: 512 chunks
        int m = q >> 2, c = q & 3;
        srcA[p] = A + (bm + m)*lda + c*8;
        dstA[p] = gs + m*HSTRIDE + c*4;
    }
    #pragma unroll
    for (int p=0;p<4;p++){
        int qb = tid + p*256;            // B: 1024 chunks
        int n = qb >> 2, c = qb & 3;
        srcB[p] = W + (bn + n)*ldw + c*8;
        dstB[p] = gs + 128*HSTRIDE + n*HSTRIDE + c*4;
    }
    const int iters = K >> 5;

    #pragma unroll
    for (int s=0;s<2;s++){
        long k0 = (long)s*32;
        #pragma unroll
        for (int p=0;p<2;p++) cpa16(dstA[p] + s*HSTAGE, srcA[p] + k0);
        #pragma unroll
        for (int p=0;p<4;p++) cpa16(dstB[p] + s*HSTAGE, srcB[p] + k0);
        CPA_COMMIT();
    }

    for (int i = 0; i < iters; i++){
        int nstage = i + 2;
        if (nstage < iters){
            int sb = nstage - (nstage/3)*3;
            long k0 = (long)nstage*32;
            #pragma unroll
            for (int p=0;p<2;p++) cpa16(dstA[p] + sb*HSTAGE, srcA[p] + k0);
            #pragma unroll
            for (int p=0;p<4;p++) cpa16(dstB[p] + sb*HSTAGE, srcB[p] + k0);
        }
        CPA_COMMIT();
        CPA_WAIT2();
        __syncthreads();
        int cs = i - (i/3)*3;
        const uint32_t* Asm = su + cs*HSTAGE;
        const uint32_t* Bsm = Asm + 128*HSTRIDE;
        #pragma unroll
        for (int kk = 0; kk < 2; kk++){
            int kw = kk*8;
            uint32_t af[4][4], bf[8][2];
            #pragma unroll
            for (int mt=0;mt<4;mt++){
                int m0 = wm*64 + mt*16;
                af[mt][0] = Asm[(m0+r  )*HSTRIDE + kw + cl    ];
                af[mt][1] = Asm[(m0+r+8)*HSTRIDE + kw + cl    ];
                af[mt][2] = Asm[(m0+r  )*HSTRIDE + kw + cl + 4];
                af[mt][3] = Asm[(m0+r+8)*HSTRIDE + kw + cl + 4];
            }
            #pragma unroll
            for (int nt=0;nt<8;nt++){
                int n0 = wn*64 + nt*8;
                bf[nt][0] = Bsm[(n0+r)*HSTRIDE + kw + cl    ];
                bf[nt][1] = Bsm[(n0+r)*HSTRIDE + kw + cl + 4];
            }
            #pragma unroll
            for (int mt=0;mt<4;mt++)
                #pragma unroll
                for (int nt=0;nt<8;nt++)
                    mma16h(acc[mt][nt], af[mt], bf[nt]);
        }
        __syncthreads();
    }

    #pragma unroll
    for (int mt=0;mt<4;mt++){
        #pragma unroll
        for (int nt=0;nt<8;nt++){
            long row0 = bm + wm*64 + mt*16 + r;
            long col  = bn + wn*64 + nt*8 + 2*cl;
            #pragma unroll
            for (int hh=0;hh<2;hh++){
                long row = row0 + hh*8;
                float v0 = acc[mt][nt][hh*2+0];
                float v1 = acc[mt][nt][hh*2+1];
                if (bias){ v0 += bias[col]; v1 += bias[col+1]; }
                if (epi == 1){
                    float g = gate[row];
                    v0 = resid[row*ldc + col]   + g*v0;
                    v1 = resid[row*ldc + col+1] + g*v1;
                } else if (epi == 2){
                    v0 = __half2float(A[row*lda + col])   * sigf(v0);
                    v1 = __half2float(A[row*lda + col+1]) * sigf(v1);
                }
                if (outH){
                    *(__half2*)((__half*)Cv + row*ldc + col) = __floats2half2_rn(v0, v1);
                } else {
                    float2 o; o.x = v0; o.y = v1;
                    *(float2*)((float*)Cv + row*ldc + col) = o;
                }
            }
        }
    }
}

// ============================================================ small tf32 GEMM (mem heads)
__global__ void __launch_bounds__(256)
mma_gemm_small(const float* __restrict__ A, long lda, long aZ,
               const float* __restrict__ W, long ldw, long wZ,
               float* __restrict__ C, long ldc, long cZ, int K)
{
    __shared__ float As[2][16][136];
    __shared__ float Bs[2][16][136];
    int tid = threadIdx.x, lane = tid & 31, warp = tid >> 5;
    int wm = warp & 1, wn = warp >> 1;
    int r = lane >> 2, cl = lane & 3;
    long bm = (long)blockIdx.y*128, bn = (long)blockIdx.x*128;
    A += (long)blockIdx.z*aZ;
    W += (long)blockIdx.z*wZ;
    C += (long)blockIdx.z*cZ;

    float acc[4][4][4];
    #pragma unroll
    for (int i=0;i<4;i++)
        #pragma unroll
        for (int j=0;j<4;j++)
            #pragma unroll
            for (int q=0;q<4;q++) acc[i][j][q]=0.f;

    int lm = tid & 127;
    int kq = tid >> 7;
    const float* Ab = A + (bm + lm)*lda + kq*4;
    const float* Wb = W + (bn + lm)*ldw + kq*4;
    const int iters = K >> 4;
    {
        float4 a0 = *(const float4*)(Ab);
        float4 a1 = *(const float4*)(Ab + 8);
        float4 b0 = *(const float4*)(Wb);
        float4 b1 = *(const float4*)(Wb + 8);
        #pragma unroll
        for (int j=0;j<4;j++){
            As[0][kq*4+j][lm]   = ((const float*)&a0)[j];
            As[0][kq*4+8+j][lm] = ((const float*)&a1)[j];
            Bs[0][kq*4+j][lm]   = ((const float*)&b0)[j];
            Bs[0][kq*4+8+j][lm] = ((const float*)&b1)[j];
        }
    }
    __syncthreads();
    for (int i = 0; i < iters; i++){
        int bsel = i & 1;
        float4 a0, a1, b0, b1;
        if (i+1 < iters){
            const float* Ap = Ab + (long)(i+1)*16;
            const float* Wp = Wb + (long)(i+1)*16;
            a0 = *(const float4*)(Ap);  a1 = *(const float4*)(Ap + 8);
            b0 = *(const float4*)(Wp);  b1 = *(const float4*)(Wp + 8);
        }
        #pragma unroll
        for (int kk = 0; kk < 2; kk++){
            int kb = kk*8;
            uint32_t af[4][4], bf[4][2];
            #pragma unroll
            for (int mt=0;mt<4;mt++){
                int m0 = wm*64 + mt*16;
                af[mt][0] = __float_as_uint(As[bsel][kb+cl  ][m0+r  ]);
                af[mt][1] = __float_as_uint(As[bsel][kb+cl  ][m0+r+8]);
                af[mt][2] = __float_as_uint(As[bsel][kb+cl+4][m0+r  ]);
                af[mt][3] = __float_as_uint(As[bsel][kb+cl+4][m0+r+8]);
            }
            #pragma unroll
            for (int nt=0;nt<4;nt++){
                int n0 = wn*32 + nt*8;
                bf[nt][0] = __float_as_uint(Bs[bsel][kb+cl  ][n0+r]);
                bf[nt][1] = __float_as_uint(Bs[bsel][kb+cl+4][n0+r]);
            }
            #pragma unroll
            for (int mt=0;mt<4;mt++)
                #pragma unroll
                for (int nt=0;nt<4;nt++)
                    mma8(acc[mt][nt], af[mt], bf[nt]);
        }
        if (i+1 < iters){
            __syncthreads();
            int nb = (i+1)&1;
            #pragma unroll
            for (int j=0;j<4;j++){
                As[nb][kq*4+j][lm]   = ((const float*)&a0)[j];
                As[nb][kq*4+8+j][lm] = ((const float*)&a1)[j];
                Bs[nb][kq*4+j][lm]   = ((const float*)&b0)[j];
                Bs[nb][kq*4+8+j][lm] = ((const float*)&b1)[j];
            }
            __syncthreads();
        }
    }
    #pragma unroll
    for (int mt=0;mt<4;mt++){
        #pragma unroll
        for (int nt=0;nt<4;nt++){
            long row0 = bm + wm*64 + mt*16 + r;
            long col  = bn + wn*32 + nt*8 + 2*cl;
            #pragma unroll
            for (int hh=0;hh<2;hh++){
                long row = row0 + hh*8;
                float2 o; o.x = acc[mt][nt][hh*2+0]; o.y = acc[mt][nt][hh*2+1];
                *(float2*)(C + row*ldc + col) = o;
            }
        }
    }
}

// ------------------------------------------------------------ weight conversion
__global__ void __launch_bounds__(256) cvtw_kernel(
    const float4* __restrict__ in, __half2* __restrict__ out, int n4)
{
    int i = blockIdx.x*256 + threadIdx.x;
    if (i < n4){
        float4 v = in[i];
        out[2*i]   = __floats2half2_rn(v.x, v.y);
        out[2*i+1] = __floats2half2_rn(v.z, v.w);
    }
}
__global__ void __launch_bounds__(256) roundw_kernel(
    const float4* __restrict__ in, float4* __restrict__ out, int n4)
{
    int i = blockIdx.x*256 + threadIdx.x;
    if (i < n4){
        float4 v = in[i];
        v.x = rtf(v.x); v.y = rtf(v.y); v.z = rtf(v.z); v.w = rtf(v.w);
        out[i] = v;
    }
}

// ------------------------------------------------------------ rms + gate (+router)
__global__ void __launch_bounds__(256) rms_router_kernel(
    const float* __restrict__ x, const float* __restrict__ nw,
    const float* __restrict__ gw, const float* __restrict__ gb,
    float* __restrict__ y, __half* __restrict__ yh, float* __restrict__ gate,
    const float* __restrict__ rw, const float* __restrict__ rb,
    float* __restrict__ hw)
{
    __shared__ float sy[HDIM];
    __shared__ float red[256];
    int t = blockIdx.x, tid = threadIdx.x;
    const float* xr = x + (size_t)t*HDIM;
    float ss = 0.f, gd = 0.f;
    for (int i = tid; i < HDIM; i += 256){
        float v = xr[i]; sy[i] = v; ss += v*v; gd += v*gw[i];
    }
    red[tid] = ss; __syncthreads();
    for (int s = 128; s > 0; s >>= 1){ if (tid < s) red[tid] += red[tid+s]; __syncthreads(); }
    float rs = rsqrtf(red[0]*(1.f/HDIM) + 1e-6f);
    __syncthreads();
    red[tid] = gd; __syncthreads();
    for (int s = 128; s > 0; s >>= 1){ if (tid < s) red[tid] += red[tid+s]; __syncthreads(); }
    if (tid == 0) gate[t] = sigf(red[0] + gb[0]);
    for (int i = tid; i < HDIM; i += 256){
        float v = sy[i]*rs*nw[i];
        if (y)  y[(size_t)t*HDIM + i] = v;
        if (yh) yh[(size_t)t*HDIM + i] = __float2half_rn(v);
        sy[i] = v;
    }
    if (rw){
        __syncthreads();
        int warp = tid >> 5, lane = tid & 31;
        for (int r = warp; r < NHEADS; r += 8){
            float s = 0.f;
            for (int i = lane; i < HDIM; i += 32) s += sy[i]*rw[r*HDIM + i];
            #pragma unroll
            for (int o = 16; o; o >>= 1) s += __shfl_down_sync(0xffffffffu, s, o);
            if (lane == 0) hw[(size_t)t*NHEADS + r] = sigf(s + rb[r]);
        }
    }
}

// ------------------------------------------------------------ fused 6-stage conv stack
__global__ void __launch_bounds__(256) convfused_kernel(
    const float* __restrict__ in, __half* __restrict__ out,
    const float* __restrict__ w, const float* __restrict__ b)
{
    extern __shared__ float cs[];
    float* buf0 = cs;
    float* buf1 = cs + SL*8;
    int cg = blockIdx.x % (HDIM/8);
    int bb = blockIdx.x / (HDIM/8);
    int c0 = cg*8;
    int tid = threadIdx.x;
    const float* base = in + (size_t)bb*SL*HDIM + c0;
    for (int e = tid; e < SL*8; e += 256){
        int t = e >> 3, c = e & 7;
        buf0[e] = base[(size_t)t*HDIM + c];
    }
    __syncthreads();
    float* src = buf0; float* dst = buf1;
    int c = tid & 7;
    #pragma unroll
    for (int j = 0; j < 6; j++){
        int dil = 1 << j;
        float w0 = w[(j*HDIM + c0 + c)*KW + 0];
        float w1 = w[(j*HDIM + c0 + c)*KW + 1];
        float w2 = w[(j*HDIM + c0 + c)*KW + 2];
        float w3 = w[(j*HDIM + c0 + c)*KW + 3];
        float bj = b[j*HDIM + c0 + c];
        for (int t = tid >> 3; t < SL; t += 32){
            float xv = src[t*8 + c];
            float a = bj + xv*w3;
            int t1 = t - dil, t2 = t - 2*dil, t3 = t - 3*dil;
            if (t1 >= 0) a += src[t1*8 + c]*w2;
            if (t2 >= 0) a += src[t2*8 + c]*w1;
            if (t3 >= 0) a += src[t3*8 + c]*w0;
            dst[t*8 + c] = xv + geluf(a);
        }
        __syncthreads();
        float* tmp = src; src = dst; dst = tmp;
    }
    __half* obase = out + (size_t)bb*SL*HDIM + c0;
    for (int e = tid; e < SL*8; e += 256){
        int t = e >> 3, cc = e & 7;
        obase[(size_t)t*HDIM + cc] = __float2half_rn(src[e]);
    }
}

// ------------------------------------------------------------ per-head conv (float4)
__global__ void __launch_bounds__(256) headconv_v4(
    const float4* __restrict__ in, float4* __restrict__ out,
    const float* __restrict__ w, const float* __restrict__ b, int stage)
{
    const int C4 = HDIM/4;
    int idx = blockIdx.x*256 + threadIdx.x;
    int c4 = idx % C4;
    int tok = idx / C4;
    int t = tok & (SL-1);
    int head = c4 >> 5;
    int d = (c4 & 31)*4;
    int dil = c_dils[head][stage];
    int wb = (head*3 + stage)*HDH + d;
    float4 acc = *(const float4*)(b + wb);
    float4 xv = in[idx];
    #pragma unroll
    for (int k = 0; k < KW-1; k++){
        int tt = t - (KW-1-k)*dil;
        if (tt >= 0){
            float4 iv = in[idx + (tt - t)*C4];
            acc.x += iv.x * w[(wb+0)*KW + k];
            acc.y += iv.y * w[(wb+1)*KW + k];
            acc.z += iv.z * w[(wb+2)*KW + k];
            acc.w += iv.w * w[(wb+3)*KW + k];
        }
    }
    acc.x += xv.x * w[(wb+0)*KW + 3];
    acc.y += xv.y * w[(wb+1)*KW + 3];
    acc.z += xv.z * w[(wb+2)*KW + 3];
    acc.w += xv.w * w[(wb+3)*KW + 3];
    float4 o; o.x = xv.x + acc.x; o.y = xv.y + acc.y; o.z = xv.z + acc.z; o.w = xv.w + acc.w;
    out[idx] = o;
}

// ------------------------------------------------------------ combine heads -> half
__global__ void __launch_bounds__(256) combine_h(
    const float4* __restrict__ hbuf, const float4* __restrict__ memout,
    const float* __restrict__ hw, __half2* __restrict__ out)
{
    const int C4 = HDIM/4;
    int idx = blockIdx.x*256 + threadIdx.x;
    int c4 = idx % C4;
    long tok = idx / C4;
    int head = c4 >> 5;
    float4 v = hbuf[idx];
    if (head >= 6 && head <= 9){
        float4 mv = memout[tok*128 + (head-6)*32 + (c4 & 31)];
        v.x += mv.x; v.y += mv.y; v.z += mv.z; v.w += mv.w;
    }
    float g = hw[tok*NHEADS + head];
    out[2*idx]   = __floats2half2_rn(v.x*g, v.y*g);
    out[2*idx+1] = __floats2half2_rn(v.z*g, v.w*g);
}

// ------------------------------------------------------------ GLU variants
__global__ void __launch_bounds__(256) glu_f32(
    const float4* __restrict__ big, float4* __restrict__ out, int N4)
{
    long idx = (long)blockIdx.x*256 + threadIdx.x;
    if (idx >= (long)NT*N4) return;
    long m = idx / N4; int n = (int)(idx % N4);
    float4 c = big[m*2*N4 + n];
    float4 g = big[m*2*N4 + N4 + n];
    float4 o;
    o.x = rtf(c.x*sigf(g.x)); o.y = rtf(c.y*sigf(g.y));
    o.z = rtf(c.z*sigf(g.z)); o.w = rtf(c.w*sigf(g.w));
    out[idx] = o;
}
__global__ void __launch_bounds__(256) glu_h(
    const float4* __restrict__ big, __half2* __restrict__ out, int N4)
{
    long idx = (long)blockIdx.x*256 + threadIdx.x;
    if (idx >= (long)NT*N4) return;
    long m = idx / N4; int n = (int)(idx % N4);
    float4 c = big[m*2*N4 + n];
    float4 g = big[m*2*N4 + N4 + n];
    out[2*idx]   = __floats2half2_rn(c.x*sigf(g.x), c.y*sigf(g.y));
    out[2*idx+1] = __floats2half2_rn(c.z*sigf(g.z), c.w*sigf(g.w));
}

// ------------------------------------------------------------ memory write-gate
__global__ void __launch_bounds__(128) memgate_kernel(
    const float* __restrict__ xh, const float* __restrict__ wg,
    const float* __restrict__ bg, float* __restrict__ g)
{
    __shared__ float red[128];
    int t = blockIdx.x, tid = threadIdx.x;
    for (int h = 0; h < 4; h++){
        float v = xh[(size_t)t*HDIM + (6+h)*HDH + tid] * wg[h*HDH + tid];
        red[tid] = v; __syncthreads();
        for (int s = 64; s > 0; s >>= 1){ if (tid < s) red[tid] += red[tid+s]; __syncthreads(); }
        if (tid == 0) g[t*4 + h] = sigf(red[0] + bg[h]);
        __syncthreads();
    }
}

// ------------------------------------------------------------ memory scan
#define SCAN_SMEM ((64*QS*2 + 64*MT + 64 + 128*(MT+1) + 4)*4)
__global__ void __launch_bounds__(256) memscan_kernel(
    const float* __restrict__ q, const float* __restrict__ k,
    const float* __restrict__ v, const float* __restrict__ g,
    float* __restrict__ reads)
{
    extern __shared__ float smem[];
    float* sQ  = smem;
    float* sK  = sQ + 64*QS;
    float* sV  = sK + 64*QS;
    float* sG  = sV + 64*MT;
    float* sM  = sG + 64;
    float* sDec= sM + 128*(MT+1);
    int tid  = threadIdx.x;
    int mblk = blockIdx.x & 15;
    int h    = (blockIdx.x >> 4) & 3;
    int b    = blockIdx.x >> 6;
    int m0   = mblk * MT;
    for (int i = tid; i < 128*(MT+1); i += 256) sM[i] = 0.f;
    for (int c = 0; c < NCHUNK; c++){
        int tok0 = b*SL + c*CHUNK;
        __syncthreads();
        if (tid < 64) sG[tid] = g[(tok0 + tid)*4 + h];
        __syncthreads();
        #pragma unroll
        for (int it = 0; it < 8; it++){
            int li = tid + it*256;
            int s  = li >> 5;
            int e4 = (li & 31) << 2;
            size_t gi = ((size_t)(tok0 + s)*4 + h)*HDH + e4;
            float4 qa = *(const float4*)(q + gi);
            float4 ka = *(const float4*)(k + gi);
            float gs = sG[s];
            int so = s*QS + e4;
            sQ[so] = qa.x; sQ[so+1] = qa.y; sQ[so+2] = qa.z; sQ[so+3] = qa.w;
            sK[so] = ka.x*gs; sK[so+1] = ka.y*gs; sK[so+2] = ka.z*gs; sK[so+3] = ka.w*gs;
        }
        if (tid < 128){
            int s = tid >> 1; int mm = (tid & 1)*4;
            float4 va = *(const float4*)(v + ((size_t)(tok0 + s)*4 + h)*HDH + m0 + mm);
            float* dv = &sV[s*MT + mm];
            dv[0]=va.x; dv[1]=va.y; dv[2]=va.z; dv[3]=va.w;
        }
        __syncthreads();
        if (tid < 32){
            float dsum = sG[tid] + sG[tid + 32];
            #pragma unroll
            for (int o = 16; o; o >>= 1) dsum += __shfl_down_sync(0xffffffffu, dsum, o);
            if (tid == 0) sDec[0] = 1.f - dsum*(1.f/64.f);
        }
        {
            int s  = tid & 63;
            int mi = (tid >> 6)*2;
            float a0 = 0.f, a1 = 0.f;
            const float* qr = sQ + s*QS;
            #pragma unroll 8
            for (int d = 0; d < HDH; d++){
                float qv = qr[d];
                a0 += qv * sM[d*(MT+1) + mi];
                a1 += qv * sM[d*(MT+1) + mi + 1];
            }
            size_t ro = ((size_t)(tok0 + s)*4 + h)*HDH + m0 + mi;
            reads[ro] = rtf(a0); reads[ro+1] = rtf(a1);
        }
        __syncthreads();
        {
            int d  = tid & 127;
            int mb = (tid >> 7)*4;
            float dec = sDec[0];
            float a0 = dec*sM[d*(MT+1)+mb+0];
            float a1 = dec*sM[d*(MT+1)+mb+1];
            float a2 = dec*sM[d*(MT+1)+mb+2];
            float a3 = dec*sM[d*(MT+1)+mb+3];
            #pragma unroll 8
            for (int s = 0; s < 64; s++){
                float kgv = sK[s*QS + d];
                const float* vr = sV + s*MT + mb;
                a0 += kgv*vr[0]; a1 += kgv*vr[1]; a2 += kgv*vr[2]; a3 += kgv*vr[3];
            }
            sM[d*(MT+1)+mb+0]=a0; sM[d*(MT+1)+mb+1]=a1;
            sM[d*(MT+1)+mb+2]=a2; sM[d*(MT+1)+mb+3]=a3;
        }
    }
}

// ------------------------------------------------------------ host side
template<typename T>
static T* F(const void* sym){
    void* p = nullptr;
    cudaGetSymbolAddress(&p, sym);
    return (T*)p;
}

#define GEMMH_SMEM (3*HSTAGE*4)
#define CONV_SMEM  (2*SL*8*4)

static void gemmH(const __half* A, const __half* W, void* C,
                  long lda, long ldw, long ldc, int M, int N, int K,
                  int epi, int outH, const float* bias,
                  const float* resid, const float* gate)
{
    dim3 g(N/256, M/128, 1);
    mma_gemm_h<<<g, 256, GEMMH_SMEM>>>(A, lda, W, ldw, C, ldc,
                                       K, epi, outH, bias, resid, gate);
}
static void gemmMem(const float* A, long lda, long aZ,
                    const float* W, float* C, long cZ)
{
    dim3 g(1, NT/128, 4);
    mma_gemm_small<<<g, 256>>>(A, lda, aZ, W, 128, 16384, C, 512, cZ, 128);
}
static void cvtw(const float* in, __half* out, size_t n){
    int n4 = (int)(n/4);
    cvtw_kernel<<<(n4 + 255)/256, 256>>>((const float4*)in, (__half2*)out, n4);
}
static void roundw(const float* in, float* out, size_t n){
    int n4 = (int)(n/4);
    roundw_kernel<<<(n4 + 255)/256, 256>>>((const float4*)in, (float4*)out, n4);
}

extern "C" void kernel_launch(void* const* d_in, const int* in_sizes, int n_in,
                              void* d_out, int out_size)
{
    const float* x            = (const float*)d_in[0];
    const float* norm1_w      = (const float*)d_in[1];
    const float* norm2_w      = (const float*)d_in[2];
    const float* norm3_w      = (const float*)d_in[3];
    const float* convstack_w  = (const float*)d_in[4];
    const float* convstack_b  = (const float*)d_in[5];
    const float* conv_proj_w  = (const float*)d_in[6];
    const float* conv_proj_b  = (const float*)d_in[7];
    const float* gate_proj_w  = (const float*)d_in[8];
    const float* head_router_w= (const float*)d_in[9];
    const float* head_router_b= (const float*)d_in[10];
    const float* head_conv_w  = (const float*)d_in[11];
    const float* head_conv_b  = (const float*)d_in[12];
    const float* mem_Wq       = (const float*)d_in[13];
    const float* mem_Wk       = (const float*)d_in[14];
    const float* mem_Wv       = (const float*)d_in[15];
    const float* mem_Wg_w     = (const float*)d_in[16];
    const float* mem_Wg_b     = (const float*)d_in[17];
    const float* mem_Wout     = (const float*)d_in[18];
    const float* mix_gate_w   = (const float*)d_in[19];
    const float* mix_gate_b   = (const float*)d_in[20];
    const float* mixing_w     = (const float*)d_in[21];
    const float* mixing_b     = (const float*)d_in[22];
    const float* ffn_in_w     = (const float*)d_in[23];
    const float* ffn_out_w    = (const float*)d_in[24];
    const float* conv_gate_w  = (const float*)d_in[25];
    const float* conv_gate_b  = (const float*)d_in[26];
    const float* state_gate_w = (const float*)d_in[27];
    const float* state_gate_b = (const float*)d_in[28];
    const float* ffn_gate_w   = (const float*)d_in[29];
    const float* ffn_gate_b   = (const float*)d_in[30];
    float* out = (float*)d_out;

    float*  y    = F<float>(g_y);
    float*  h2a  = F<float>(g_h2a);
    float*  xh   = F<float>(g_xh);
    float*  h2   = F<float>(g_h2);
    float*  big  = F<float>(g_big);
    float*  qb   = F<float>(g_q);
    float*  kb   = F<float>(g_k);
    float*  vb   = F<float>(g_v);
    float*  rd   = F<float>(g_rd);
    float*  mo   = F<float>(g_mo);
    float*  gm   = F<float>(g_gm);
    float*  hw   = F<float>(g_hw);
    float*  gate = F<float>(g_gate);
    float*  wr   = F<float>(g_wr);
    __half* hy   = F<__half>(g_hy);
    __half* ht0  = F<__half>(g_ht0);
    __half* htc  = F<__half>(g_htc);
    __half* ht1  = F<__half>(g_ht1);
    __half* hffn = F<__half>(g_hffn);
    __half* hwt  = F<__half>(g_hwt);

    // fp16 weight offsets
    __half* hw_cp = hwt;                // conv_proj  2359296
    __half* hw_gp = hwt + 2359296;      // gate_proj  4718592
    __half* hw_mg = hwt + 7077888;      // mix_gate   2359296
    __half* hw_mx = hwt + 9437184;      // mixing     2359296
    __half* hw_fi = hwt + 11796480;     // ffn_in    18874368
    __half* hw_fo = hwt + 30670848;     // ffn_out    9437184
    // tf32 mem weights
    float* w_q = wr;
    float* w_k = wr + 65536;
    float* w_v = wr + 131072;
    float* w_o = wr + 196608;

    cudaFuncSetAttribute(memscan_kernel,
        cudaFuncAttributeMaxDynamicSharedMemorySize, SCAN_SMEM);
    cudaFuncSetAttribute(mma_gemm_h,
        cudaFuncAttributeMaxDynamicSharedMemorySize, GEMMH_SMEM);
    cudaFuncSetAttribute(convfused_kernel,
        cudaFuncAttributeMaxDynamicSharedMemorySize, CONV_SMEM);

    const int EW4 = NT*HDIM/4/256;

    // weight conversion
    cvtw(conv_proj_w, hw_cp, 2359296);
    cvtw(gate_proj_w, hw_gp, 4718592);
    cvtw(mix_gate_w,  hw_mg, 2359296);
    cvtw(mixing_w,    hw_mx, 2359296);
    cvtw(ffn_in_w,    hw_fi, 18874368);
    cvtw(ffn_out_w,   hw_fo, 9437184);
    roundw(mem_Wq, w_q, 65536);
    roundw(mem_Wk, w_k, 65536);
    roundw(mem_Wv, w_v, 65536);
    roundw(mem_Wout, w_o, 65536);

    // ============ stage A: conv branch ============
    rms_router_kernel<<<NT,256>>>(x, norm1_w, conv_gate_w, conv_gate_b,
                                  y, nullptr, gate, nullptr, nullptr, nullptr);
    convfused_kernel<<<BB*(HDIM/8), 256, CONV_SMEM>>>(y, ht0,
                                  convstack_w, convstack_b);
    gemmH(ht0, hw_cp, out, HDIM, HDIM, HDIM, NT, HDIM, HDIM, 1, 0,
          conv_proj_b, x, gate);

    // ============ stage B: state branch ============
    rms_router_kernel<<<NT,256>>>(out, norm2_w, state_gate_w, state_gate_b,
                                  nullptr, hy, gate, head_router_w, head_router_b, hw);
    gemmH(hy, hw_gp, big, HDIM, HDIM, 2*HDIM, NT, 2*HDIM, HDIM, 0, 0,
          nullptr, nullptr, nullptr);
    glu_f32<<<EW4,256>>>((const float4*)big, (float4*)xh, HDIM/4);
    memgate_kernel<<<NT,128>>>(xh, mem_Wg_w, mem_Wg_b, gm);
    gemmMem(xh + 6*HDH, HDIM, HDH, w_q, qb, HDH);
    gemmMem(xh + 6*HDH, HDIM, HDH, w_k, kb, HDH);
    gemmMem(xh + 6*HDH, HDIM, HDH, w_v, vb, HDH);
    memscan_kernel<<<BB*4*(MEMD/MT), 256, SCAN_SMEM>>>(qb, kb, vb, gm, rd);
    gemmMem(rd, 512, HDH, w_o, mo, HDH);
    headconv_v4<<<EW4,256>>>((const float4*)xh, (float4*)h2, head_conv_w, head_conv_b, 0);
    headconv_v4<<<EW4,256>>>((const float4*)h2, (float4*)h2a, head_conv_w, head_conv_b, 1);
    headconv_v4<<<EW4,256>>>((const float4*)h2a, (float4*)h2, head_conv_w, head_conv_b, 2);
    combine_h<<<EW4,256>>>((const float4*)h2, (const float4*)mo, hw, (__half2*)htc);
    gemmH(htc, hw_mg, ht1, HDIM, HDIM, HDIM, NT, HDIM, HDIM, 2, 1,
          mix_gate_b, nullptr, nullptr);
    gemmH(ht1, hw_mx, out, HDIM, HDIM, HDIM, NT, HDIM, HDIM, 1, 0,
          mixing_b, out, gate);

    // ============ stage C: FFN ============
    rms_router_kernel<<<NT,256>>>(out, norm3_w, ffn_gate_w, ffn_gate_b,
                                  nullptr, hy, gate, nullptr, nullptr, nullptr);
    gemmH(hy, hw_fi, big, HDIM, HDIM, 2*INNERD, NT, 2*INNERD, HDIM, 0, 0,
          nullptr, nullptr, nullptr);
    glu_h<<<(NT*INNERD/4 + 255)/256, 256>>>((const float4*)big, (__half2*)hffn, INNERD/4);
    gemmH(hffn, hw_fo, out, INNERD, INNERD, HDIM, NT, HDIM, INNERD, 1, 0,
          nullptr, out, gate);
}